// round 1
// baseline (speedup 1.0000x reference)
#include <cuda_runtime.h>
#include <math.h>

#define S_LEN   2048
#define DMODEL  2048
#define NHEADS  16
#define DK      128
#define NBATCH  4

// ---------------- static device scratch (no allocations allowed) ----------
__device__ float g_q[(size_t)NBATCH * S_LEN * DMODEL];     // 64 MB
__device__ float g_k[(size_t)NBATCH * S_LEN * DMODEL];     // 64 MB
__device__ float g_v[(size_t)NBATCH * S_LEN * DMODEL];     // 64 MB
__device__ float g_attn[(size_t)NBATCH * S_LEN * DMODEL];  // 64 MB
__device__ float g_logits[(size_t)NBATCH * NHEADS * S_LEN * S_LEN]; // 1.07 GB

// ---------------------------------------------------------------------------
// NT GEMM: C[m,n] = alpha * sum_k A[m,k] * B[n,k]
// Batched over blockIdx.z with (b,h) decomposition: z = b*16 + h.
// Block tile 64x64, BK=16, 256 threads, 4x4 microtile per thread.
// ---------------------------------------------------------------------------
__global__ __launch_bounds__(256) void gemm_nt(
    const float* __restrict__ A, const float* __restrict__ B, float* __restrict__ C,
    int K, int lda, int ldb, int ldc,
    size_t sAb, size_t sAh, size_t sBb, size_t sBh, size_t sCb, size_t sCh,
    float alpha)
{
    const int z = blockIdx.z;
    const int bb = z >> 4, hh = z & 15;
    A += (size_t)bb * sAb + (size_t)hh * sAh;
    B += (size_t)bb * sBb + (size_t)hh * sBh;
    C += (size_t)bb * sCb + (size_t)hh * sCh;

    __shared__ float As[16][64];
    __shared__ float Bs[16][64];

    const int tid = threadIdx.x;
    const int tx = tid & 15;
    const int ty = tid >> 4;
    const int row0 = blockIdx.y * 64;
    const int col0 = blockIdx.x * 64;
    const int lr = tid >> 2;          // 0..63 : tile row being loaded
    const int lk = (tid & 3) << 2;    // 0,4,8,12 : k offset of float4

    const float* Aptr = A + (size_t)(row0 + lr) * lda + lk;
    const float* Bptr = B + (size_t)(col0 + lr) * ldb + lk;

    float acc[4][4];
#pragma unroll
    for (int i = 0; i < 4; i++)
#pragma unroll
        for (int j = 0; j < 4; j++) acc[i][j] = 0.0f;

    for (int k0 = 0; k0 < K; k0 += 16) {
        float4 a4 = *(const float4*)(Aptr + k0);
        float4 b4 = *(const float4*)(Bptr + k0);
        As[lk + 0][lr] = a4.x; As[lk + 1][lr] = a4.y;
        As[lk + 2][lr] = a4.z; As[lk + 3][lr] = a4.w;
        Bs[lk + 0][lr] = b4.x; Bs[lk + 1][lr] = b4.y;
        Bs[lk + 2][lr] = b4.z; Bs[lk + 3][lr] = b4.w;
        __syncthreads();
#pragma unroll
        for (int k = 0; k < 16; k++) {
            float4 av = *(const float4*)&As[k][ty << 2];
            float4 bv = *(const float4*)&Bs[k][tx << 2];
            float ar[4] = {av.x, av.y, av.z, av.w};
            float br[4] = {bv.x, bv.y, bv.z, bv.w};
#pragma unroll
            for (int i = 0; i < 4; i++)
#pragma unroll
                for (int j = 0; j < 4; j++)
                    acc[i][j] = fmaf(ar[i], br[j], acc[i][j]);
        }
        __syncthreads();
    }

#pragma unroll
    for (int i = 0; i < 4; i++) {
        float* crow = C + (size_t)(row0 + (ty << 2) + i) * ldc + col0 + (tx << 2);
        float4 o;
        o.x = acc[i][0] * alpha; o.y = acc[i][1] * alpha;
        o.z = acc[i][2] * alpha; o.w = acc[i][3] * alpha;
        *(float4*)crow = o;
    }
}

// ---------------------------------------------------------------------------
// NN GEMM: C[m,n] = alpha * sum_k A[m,k] * B[k,n]   (batched, same tiling)
// ---------------------------------------------------------------------------
__global__ __launch_bounds__(256) void gemm_nn(
    const float* __restrict__ A, const float* __restrict__ B, float* __restrict__ C,
    int K, int lda, int ldb, int ldc,
    size_t sAb, size_t sAh, size_t sBb, size_t sBh, size_t sCb, size_t sCh,
    float alpha)
{
    const int z = blockIdx.z;
    const int bb = z >> 4, hh = z & 15;
    A += (size_t)bb * sAb + (size_t)hh * sAh;
    B += (size_t)bb * sBb + (size_t)hh * sBh;
    C += (size_t)bb * sCb + (size_t)hh * sCh;

    __shared__ float As[16][64];
    __shared__ float Bs[16][64];

    const int tid = threadIdx.x;
    const int tx = tid & 15;
    const int ty = tid >> 4;
    const int row0 = blockIdx.y * 64;
    const int col0 = blockIdx.x * 64;

    // A load (transpose into smem): same as NT
    const int lr = tid >> 2;
    const int lk = (tid & 3) << 2;
    const float* Aptr = A + (size_t)(row0 + lr) * lda + lk;

    // B load (direct): 16 k-rows x 64 n-cols
    const int lkr = tid >> 4;          // 0..15
    const int ln  = (tid & 15) << 2;   // 0..60
    const float* Bptr = B + (size_t)lkr * ldb + col0 + ln;

    float acc[4][4];
#pragma unroll
    for (int i = 0; i < 4; i++)
#pragma unroll
        for (int j = 0; j < 4; j++) acc[i][j] = 0.0f;

    for (int k0 = 0; k0 < K; k0 += 16) {
        float4 a4 = *(const float4*)(Aptr + k0);
        float4 b4 = *(const float4*)(Bptr + (size_t)k0 * ldb);
        As[lk + 0][lr] = a4.x; As[lk + 1][lr] = a4.y;
        As[lk + 2][lr] = a4.z; As[lk + 3][lr] = a4.w;
        *(float4*)&Bs[lkr][ln] = b4;
        __syncthreads();
#pragma unroll
        for (int k = 0; k < 16; k++) {
            float4 av = *(const float4*)&As[k][ty << 2];
            float4 bv = *(const float4*)&Bs[k][tx << 2];
            float ar[4] = {av.x, av.y, av.z, av.w};
            float br[4] = {bv.x, bv.y, bv.z, bv.w};
#pragma unroll
            for (int i = 0; i < 4; i++)
#pragma unroll
                for (int j = 0; j < 4; j++)
                    acc[i][j] = fmaf(ar[i], br[j], acc[i][j]);
        }
        __syncthreads();
    }

#pragma unroll
    for (int i = 0; i < 4; i++) {
        float* crow = C + (size_t)(row0 + (ty << 2) + i) * ldc + col0 + (tx << 2);
        float4 o;
        o.x = acc[i][0] * alpha; o.y = acc[i][1] * alpha;
        o.z = acc[i][2] * alpha; o.w = acc[i][3] * alpha;
        *(float4*)crow = o;
    }
}

// ---------------------------------------------------------------------------
// Row softmax in place: one 256-thread block per row.
// ---------------------------------------------------------------------------
__global__ __launch_bounds__(256) void softmax_rows(float* __restrict__ X, int ncols)
{
    const size_t row = blockIdx.x;
    float* x = X + row * (size_t)ncols;
    const int tid = threadIdx.x;
    const int lane = tid & 31, warp = tid >> 5;

    __shared__ float red_max[8];
    __shared__ float red_sum[8];

    float m = -3.0e38f;
    for (int i = tid; i < ncols; i += 256) m = fmaxf(m, x[i]);
#pragma unroll
    for (int o = 16; o > 0; o >>= 1) m = fmaxf(m, __shfl_xor_sync(0xffffffffu, m, o));
    if (lane == 0) red_max[warp] = m;
    __syncthreads();
    m = red_max[0];
#pragma unroll
    for (int w = 1; w < 8; w++) m = fmaxf(m, red_max[w]);

    float s = 0.0f;
    for (int i = tid; i < ncols; i += 256) {
        float e = __expf(x[i] - m);
        x[i] = e;
        s += e;
    }
#pragma unroll
    for (int o = 16; o > 0; o >>= 1) s += __shfl_xor_sync(0xffffffffu, s, o);
    if (lane == 0) red_sum[warp] = s;
    __syncthreads();
    s = red_sum[0];
#pragma unroll
    for (int w = 1; w < 8; w++) s += red_sum[w];
    const float inv = 1.0f / s;

    for (int i = tid; i < ncols; i += 256) x[i] *= inv;
}

// ---------------------------------------------------------------------------
extern "C" void kernel_launch(void* const* d_in, const int* in_sizes, int n_in,
                              void* d_out, int out_size)
{
    const float* q   = (const float*)d_in[0];
    const float* k   = (const float*)d_in[1];
    const float* v   = (const float*)d_in[2];
    const float* w_q = (const float*)d_in[3];
    const float* w_k = (const float*)d_in[4];
    const float* w_v = (const float*)d_in[5];
    const float* w_o = (const float*)d_in[6];
    float* out = (float*)d_out;

    float *gq, *gk, *gv, *gattn, *glog;
    cudaGetSymbolAddress((void**)&gq, g_q);
    cudaGetSymbolAddress((void**)&gk, g_k);
    cudaGetSymbolAddress((void**)&gv, g_v);
    cudaGetSymbolAddress((void**)&gattn, g_attn);
    cudaGetSymbolAddress((void**)&glog, g_logits);

    const int M_rows = NBATCH * S_LEN;                 // 8192
    const size_t SD  = (size_t)S_LEN * DMODEL;         // per-batch q/k/v stride
    const size_t SS  = (size_t)S_LEN * S_LEN;          // per-head logits stride
    const float inv_sqrt_dk = 1.0f / sqrtf((float)DK);

    dim3 blk(256);

    // 1) Projections: X @ W^T  (M=8192, N=2048, K=2048)
    {
        dim3 grid(DMODEL / 64, M_rows / 64, 1);
        gemm_nt<<<grid, blk>>>(q, w_q, gq, DMODEL, DMODEL, DMODEL, DMODEL,
                               0, 0, 0, 0, 0, 0, 1.0f);
        gemm_nt<<<grid, blk>>>(k, w_k, gk, DMODEL, DMODEL, DMODEL, DMODEL,
                               0, 0, 0, 0, 0, 0, 1.0f);
        gemm_nt<<<grid, blk>>>(v, w_v, gv, DMODEL, DMODEL, DMODEL, DMODEL,
                               0, 0, 0, 0, 0, 0, 1.0f);
    }

    // 2) Logits: per (b,h), Qh @ Kh^T / sqrt(Dk)   (M=N=2048, K=128)
    {
        dim3 grid(S_LEN / 64, S_LEN / 64, NBATCH * NHEADS);
        gemm_nt<<<grid, blk>>>(gq, gk, glog, DK, DMODEL, DMODEL, S_LEN,
                               SD, (size_t)DK,          // A: Q  (b-stride, h-stride)
                               SD, (size_t)DK,          // B: K
                               (size_t)NHEADS * SS, SS, // C: logits
                               inv_sqrt_dk);
    }

    // 3) Softmax over last dim: B*H*S rows of length S
    softmax_rows<<<NBATCH * NHEADS * S_LEN, blk>>>(glog, S_LEN);

    // 4) Attn = P @ Vh  (NN, M=2048, N=128, K=2048), written head-interleaved
    {
        dim3 grid(DK / 64, S_LEN / 64, NBATCH * NHEADS);
        gemm_nn<<<grid, blk>>>(glog, gv, gattn, S_LEN, S_LEN, DMODEL, DMODEL,
                               (size_t)NHEADS * SS, SS, // A: probs
                               SD, (size_t)DK,          // B: V
                               SD, (size_t)DK,          // C: attn [B,S,H*Dk]
                               1.0f);
    }

    // 5) Output projection: attn @ W_o^T  (M=8192, N=2048, K=2048)
    {
        dim3 grid(DMODEL / 64, M_rows / 64, 1);
        gemm_nt<<<grid, blk>>>(gattn, w_o, out, DMODEL, DMODEL, DMODEL, DMODEL,
                               0, 0, 0, 0, 0, 0, 1.0f);
    }
}

// round 2
// speedup vs baseline: 1.3060x; 1.3060x over previous
#include <cuda_runtime.h>
#include <math.h>

#define S_LEN   2048
#define DMODEL  2048
#define NHEADS  16
#define DK      128
#define NBATCH  4

// ---------------- static device scratch (no allocations allowed) ----------
__device__ float g_q[(size_t)NBATCH * S_LEN * DMODEL];     // 64 MB
__device__ float g_k[(size_t)NBATCH * S_LEN * DMODEL];     // 64 MB
__device__ float g_v[(size_t)NBATCH * S_LEN * DMODEL];     // 64 MB
__device__ float g_attn[(size_t)NBATCH * S_LEN * DMODEL];  // 64 MB
__device__ float g_logits[(size_t)NBATCH * NHEADS * S_LEN * S_LEN]; // 1.07 GB

// ===========================================================================
// 128x128 block tile, BK=8, 256 threads, 8x8 microtile, double-buffered smem.
// NT:  C[m,n] = alpha * sum_k A[m,k] * B[n,k]
// ===========================================================================
__global__ __launch_bounds__(256) void gemm_nt(
    const float* __restrict__ A, const float* __restrict__ B, float* __restrict__ C,
    int K, int lda, int ldb, int ldc,
    size_t sAb, size_t sAh, size_t sBb, size_t sBh, size_t sCb, size_t sCh,
    float alpha)
{
    const int z = blockIdx.z;
    const int bb = z >> 4, hh = z & 15;
    A += (size_t)bb * sAb + (size_t)hh * sAh;
    B += (size_t)bb * sBb + (size_t)hh * sBh;
    C += (size_t)bb * sCb + (size_t)hh * sCh;

    __shared__ float As[2][8][128];
    __shared__ float Bs[2][8][128];

    const int tid  = threadIdx.x;
    const int row0 = blockIdx.y * 128;
    const int col0 = blockIdx.x * 128;

    // loader indices: each thread loads one float4 of A and one of B per tile
    const int lr = tid >> 1;          // 0..127 : tile row (m for A, n for B)
    const int lk = (tid & 1) << 2;    // 0 or 4 : k offset of the float4
    const float* Aptr = A + (size_t)(row0 + lr) * lda + lk;
    const float* Bptr = B + (size_t)(col0 + lr) * ldb + lk;

    // compute indices
    const int tx = (tid & 15) << 3;   // 0..120 : n offset
    const int ty = (tid >> 4) << 3;   // 0..120 : m offset

    float acc[8][8];
#pragma unroll
    for (int i = 0; i < 8; i++)
#pragma unroll
        for (int j = 0; j < 8; j++) acc[i][j] = 0.0f;

    // preload tile 0
    {
        float4 a4 = *(const float4*)(Aptr);
        float4 b4 = *(const float4*)(Bptr);
        As[0][lk + 0][lr] = a4.x; As[0][lk + 1][lr] = a4.y;
        As[0][lk + 2][lr] = a4.z; As[0][lk + 3][lr] = a4.w;
        Bs[0][lk + 0][lr] = b4.x; Bs[0][lk + 1][lr] = b4.y;
        Bs[0][lk + 2][lr] = b4.z; Bs[0][lk + 3][lr] = b4.w;
    }
    __syncthreads();

    int buf = 0;
    for (int k0 = 8; k0 <= K; k0 += 8) {
        float4 na, nb;
        const bool has = (k0 < K);
        if (has) {
            na = *(const float4*)(Aptr + k0);
            nb = *(const float4*)(Bptr + k0);
        }
#pragma unroll
        for (int k = 0; k < 8; k++) {
            float4 a0 = *(const float4*)&As[buf][k][ty];
            float4 a1 = *(const float4*)&As[buf][k][ty + 4];
            float4 b0 = *(const float4*)&Bs[buf][k][tx];
            float4 b1 = *(const float4*)&Bs[buf][k][tx + 4];
            float ar[8] = {a0.x, a0.y, a0.z, a0.w, a1.x, a1.y, a1.z, a1.w};
            float br[8] = {b0.x, b0.y, b0.z, b0.w, b1.x, b1.y, b1.z, b1.w};
#pragma unroll
            for (int i = 0; i < 8; i++)
#pragma unroll
                for (int j = 0; j < 8; j++)
                    acc[i][j] = fmaf(ar[i], br[j], acc[i][j]);
        }
        if (has) {
            const int nb_ = buf ^ 1;
            As[nb_][lk + 0][lr] = na.x; As[nb_][lk + 1][lr] = na.y;
            As[nb_][lk + 2][lr] = na.z; As[nb_][lk + 3][lr] = na.w;
            Bs[nb_][lk + 0][lr] = nb.x; Bs[nb_][lk + 1][lr] = nb.y;
            Bs[nb_][lk + 2][lr] = nb.z; Bs[nb_][lk + 3][lr] = nb.w;
            __syncthreads();
            buf = nb_;
        }
    }

#pragma unroll
    for (int i = 0; i < 8; i++) {
        float* crow = C + (size_t)(row0 + ty + i) * ldc + col0 + tx;
        float4 o0, o1;
        o0.x = acc[i][0] * alpha; o0.y = acc[i][1] * alpha;
        o0.z = acc[i][2] * alpha; o0.w = acc[i][3] * alpha;
        o1.x = acc[i][4] * alpha; o1.y = acc[i][5] * alpha;
        o1.z = acc[i][6] * alpha; o1.w = acc[i][7] * alpha;
        *(float4*)(crow)     = o0;
        *(float4*)(crow + 4) = o1;
    }
}

// ===========================================================================
// NN:  C[m,n] = alpha * sum_k A[m,k] * B[k,n]   (same tiling)
// ===========================================================================
__global__ __launch_bounds__(256) void gemm_nn(
    const float* __restrict__ A, const float* __restrict__ B, float* __restrict__ C,
    int K, int lda, int ldb, int ldc,
    size_t sAb, size_t sAh, size_t sBb, size_t sBh, size_t sCb, size_t sCh,
    float alpha)
{
    const int z = blockIdx.z;
    const int bb = z >> 4, hh = z & 15;
    A += (size_t)bb * sAb + (size_t)hh * sAh;
    B += (size_t)bb * sBb + (size_t)hh * sBh;
    C += (size_t)bb * sCb + (size_t)hh * sCh;

    __shared__ float As[2][8][128];
    __shared__ float Bs[2][8][128];

    const int tid  = threadIdx.x;
    const int row0 = blockIdx.y * 128;
    const int col0 = blockIdx.x * 128;

    // A loader (transpose into smem, k-major)
    const int lr = tid >> 1;
    const int lk = (tid & 1) << 2;
    const float* Aptr = A + (size_t)(row0 + lr) * lda + lk;

    // B loader (direct, row-major in k): 8 k-rows x 128 n-cols
    const int kr = tid >> 5;           // 0..7
    const int ln = (tid & 31) << 2;    // 0..124
    const float* Bptr = B + (size_t)kr * ldb + col0 + ln;

    const int tx = (tid & 15) << 3;
    const int ty = (tid >> 4) << 3;

    float acc[8][8];
#pragma unroll
    for (int i = 0; i < 8; i++)
#pragma unroll
        for (int j = 0; j < 8; j++) acc[i][j] = 0.0f;

    {
        float4 a4 = *(const float4*)(Aptr);
        float4 b4 = *(const float4*)(Bptr);
        As[0][lk + 0][lr] = a4.x; As[0][lk + 1][lr] = a4.y;
        As[0][lk + 2][lr] = a4.z; As[0][lk + 3][lr] = a4.w;
        *(float4*)&Bs[0][kr][ln] = b4;
    }
    __syncthreads();

    int buf = 0;
    for (int k0 = 8; k0 <= K; k0 += 8) {
        float4 na, nb;
        const bool has = (k0 < K);
        if (has) {
            na = *(const float4*)(Aptr + k0);
            nb = *(const float4*)(Bptr + (size_t)k0 * ldb);
        }
#pragma unroll
        for (int k = 0; k < 8; k++) {
            float4 a0 = *(const float4*)&As[buf][k][ty];
            float4 a1 = *(const float4*)&As[buf][k][ty + 4];
            float4 b0 = *(const float4*)&Bs[buf][k][tx];
            float4 b1 = *(const float4*)&Bs[buf][k][tx + 4];
            float ar[8] = {a0.x, a0.y, a0.z, a0.w, a1.x, a1.y, a1.z, a1.w};
            float br[8] = {b0.x, b0.y, b0.z, b0.w, b1.x, b1.y, b1.z, b1.w};
#pragma unroll
            for (int i = 0; i < 8; i++)
#pragma unroll
                for (int j = 0; j < 8; j++)
                    acc[i][j] = fmaf(ar[i], br[j], acc[i][j]);
        }
        if (has) {
            const int nb_ = buf ^ 1;
            As[nb_][lk + 0][lr] = na.x; As[nb_][lk + 1][lr] = na.y;
            As[nb_][lk + 2][lr] = na.z; As[nb_][lk + 3][lr] = na.w;
            *(float4*)&Bs[nb_][kr][ln] = nb;
            __syncthreads();
            buf = nb_;
        }
    }

#pragma unroll
    for (int i = 0; i < 8; i++) {
        float* crow = C + (size_t)(row0 + ty + i) * ldc + col0 + tx;
        float4 o0, o1;
        o0.x = acc[i][0] * alpha; o0.y = acc[i][1] * alpha;
        o0.z = acc[i][2] * alpha; o0.w = acc[i][3] * alpha;
        o1.x = acc[i][4] * alpha; o1.y = acc[i][5] * alpha;
        o1.z = acc[i][6] * alpha; o1.w = acc[i][7] * alpha;
        *(float4*)(crow)     = o0;
        *(float4*)(crow + 4) = o1;
    }
}

// ===========================================================================
// Row softmax in place, row length fixed 2048. One 256-thread block per row.
// Row cached in registers: exactly 1 read + 1 write of the logits buffer.
// ===========================================================================
__global__ __launch_bounds__(256) void softmax_rows(float* __restrict__ X)
{
    float4* x4 = (float4*)(X + blockIdx.x * (size_t)S_LEN);
    const int tid = threadIdx.x;
    const int lane = tid & 31, warp = tid >> 5;

    __shared__ float red[8];

    float4 u = x4[tid];
    float4 w = x4[tid + 256];

    float m = fmaxf(fmaxf(fmaxf(u.x, u.y), fmaxf(u.z, u.w)),
                    fmaxf(fmaxf(w.x, w.y), fmaxf(w.z, w.w)));
#pragma unroll
    for (int o = 16; o > 0; o >>= 1) m = fmaxf(m, __shfl_xor_sync(0xffffffffu, m, o));
    if (lane == 0) red[warp] = m;
    __syncthreads();
    m = red[0];
#pragma unroll
    for (int i = 1; i < 8; i++) m = fmaxf(m, red[i]);
    __syncthreads();

    u.x = __expf(u.x - m); u.y = __expf(u.y - m);
    u.z = __expf(u.z - m); u.w = __expf(u.w - m);
    w.x = __expf(w.x - m); w.y = __expf(w.y - m);
    w.z = __expf(w.z - m); w.w = __expf(w.w - m);

    float s = (u.x + u.y) + (u.z + u.w) + (w.x + w.y) + (w.z + w.w);
#pragma unroll
    for (int o = 16; o > 0; o >>= 1) s += __shfl_xor_sync(0xffffffffu, s, o);
    if (lane == 0) red[warp] = s;
    __syncthreads();
    s = red[0];
#pragma unroll
    for (int i = 1; i < 8; i++) s += red[i];
    const float inv = 1.0f / s;

    u.x *= inv; u.y *= inv; u.z *= inv; u.w *= inv;
    w.x *= inv; w.y *= inv; w.z *= inv; w.w *= inv;
    x4[tid] = u;
    x4[tid + 256] = w;
}

// ---------------------------------------------------------------------------
extern "C" void kernel_launch(void* const* d_in, const int* in_sizes, int n_in,
                              void* d_out, int out_size)
{
    const float* q   = (const float*)d_in[0];
    const float* k   = (const float*)d_in[1];
    const float* v   = (const float*)d_in[2];
    const float* w_q = (const float*)d_in[3];
    const float* w_k = (const float*)d_in[4];
    const float* w_v = (const float*)d_in[5];
    const float* w_o = (const float*)d_in[6];
    float* out = (float*)d_out;

    float *gq, *gk, *gv, *gattn, *glog;
    cudaGetSymbolAddress((void**)&gq, g_q);
    cudaGetSymbolAddress((void**)&gk, g_k);
    cudaGetSymbolAddress((void**)&gv, g_v);
    cudaGetSymbolAddress((void**)&gattn, g_attn);
    cudaGetSymbolAddress((void**)&glog, g_logits);

    const int M_rows = NBATCH * S_LEN;                 // 8192
    const size_t SD  = (size_t)S_LEN * DMODEL;         // per-batch q/k/v stride
    const size_t SS  = (size_t)S_LEN * S_LEN;          // per-head logits stride
    const float inv_sqrt_dk = 1.0f / sqrtf((float)DK);

    dim3 blk(256);

    // 1) Projections: X @ W^T  (M=8192, N=2048, K=2048)
    {
        dim3 grid(DMODEL / 128, M_rows / 128, 1);
        gemm_nt<<<grid, blk>>>(q, w_q, gq, DMODEL, DMODEL, DMODEL, DMODEL,
                               0, 0, 0, 0, 0, 0, 1.0f);
        gemm_nt<<<grid, blk>>>(k, w_k, gk, DMODEL, DMODEL, DMODEL, DMODEL,
                               0, 0, 0, 0, 0, 0, 1.0f);
        gemm_nt<<<grid, blk>>>(v, w_v, gv, DMODEL, DMODEL, DMODEL, DMODEL,
                               0, 0, 0, 0, 0, 0, 1.0f);
    }

    // 2) Logits: per (b,h), Qh @ Kh^T / sqrt(Dk)   (M=N=2048, K=128)
    {
        dim3 grid(S_LEN / 128, S_LEN / 128, NBATCH * NHEADS);
        gemm_nt<<<grid, blk>>>(gq, gk, glog, DK, DMODEL, DMODEL, S_LEN,
                               SD, (size_t)DK,
                               SD, (size_t)DK,
                               (size_t)NHEADS * SS, SS,
                               inv_sqrt_dk);
    }

    // 3) Softmax over last dim: B*H*S rows of length S
    softmax_rows<<<NBATCH * NHEADS * S_LEN, blk>>>(glog);

    // 4) Attn = P @ Vh  (NN, M=2048, N=128, K=2048), written head-interleaved
    {
        dim3 grid(DK / 128, S_LEN / 128, NBATCH * NHEADS);
        gemm_nn<<<grid, blk>>>(glog, gv, gattn, S_LEN, S_LEN, DMODEL, DMODEL,
                               (size_t)NHEADS * SS, SS,
                               SD, (size_t)DK,
                               SD, (size_t)DK,
                               1.0f);
    }

    // 5) Output projection: attn @ W_o^T  (M=8192, N=2048, K=2048)
    {
        dim3 grid(DMODEL / 128, M_rows / 128, 1);
        gemm_nt<<<grid, blk>>>(gattn, w_o, out, DMODEL, DMODEL, DMODEL, DMODEL,
                               0, 0, 0, 0, 0, 0, 1.0f);
    }
}

// round 4
// speedup vs baseline: 2.1250x; 1.6271x over previous
#include <cuda_runtime.h>
#include <cuda_bf16.h>
#include <math.h>
#include <stdint.h>

#define S_LEN   2048
#define DMODEL  2048
#define NHEADS  16
#define DK      128
#define NBATCH  4

// ---------------- static device scratch (no allocations allowed) ----------
__device__ float g_q[(size_t)NBATCH * S_LEN * DMODEL];
__device__ float g_k[(size_t)NBATCH * S_LEN * DMODEL];
__device__ float g_v[(size_t)NBATCH * S_LEN * DMODEL];
__device__ float g_attn[(size_t)NBATCH * S_LEN * DMODEL];
__device__ float g_logits[(size_t)NBATCH * NHEADS * S_LEN * S_LEN]; // 1.07 GB
__device__ __nv_bfloat16 g_act_hi[(size_t)NBATCH * S_LEN * DMODEL];
__device__ __nv_bfloat16 g_act_lo[(size_t)NBATCH * S_LEN * DMODEL];
__device__ __nv_bfloat16 g_w_hi[(size_t)DMODEL * DMODEL];
__device__ __nv_bfloat16 g_w_lo[(size_t)DMODEL * DMODEL];

// ======================= PTX helpers =======================================
__device__ __forceinline__ uint32_t smem_u32(const void* p) {
    uint32_t a;
    asm("{ .reg .u64 t; cvta.to.shared.u64 t, %1; cvt.u32.u64 %0, t; }" : "=r"(a) : "l"(p));
    return a;
}
#define CP_ASYNC16(dst, src) asm volatile("cp.async.cg.shared.global [%0], [%1], 16;" :: "r"(dst), "l"(src))
#define CP_COMMIT()          asm volatile("cp.async.commit_group;" ::: "memory")
#define CP_WAIT0()           asm volatile("cp.async.wait_group 0;" ::: "memory")
#define CP_WAIT1()           asm volatile("cp.async.wait_group 1;" ::: "memory")

#define LDSM_X4(r0, r1, r2, r3, addr) \
    asm volatile("ldmatrix.sync.aligned.m8n8.x4.shared.b16 {%0,%1,%2,%3}, [%4];" \
        : "=r"(r0), "=r"(r1), "=r"(r2), "=r"(r3) : "r"(addr))

#define MMA_BF16(c, a, b0, b1) \
    asm volatile("mma.sync.aligned.m16n8k16.row.col.f32.bf16.bf16.f32 " \
        "{%0,%1,%2,%3},{%4,%5,%6,%7},{%8,%9},{%0,%1,%2,%3};" \
        : "+f"((c)[0]), "+f"((c)[1]), "+f"((c)[2]), "+f"((c)[3]) \
        : "r"((a)[0]), "r"((a)[1]), "r"((a)[2]), "r"((a)[3]), "r"(b0), "r"(b1))

// ===========================================================================
// bf16x3 NT GEMM via mma.sync: C[m,n] = sum_k A[m,k]*B[n,k], fp32 accum.
// A = Ahi+Alo, B = Bhi+Blo; computes hi*hi + hi*lo + lo*hi.
// Block 128x128, BK=32, 256 threads (8 warps, 4x2), cp.async double buffer.
// smem per stage: Ahi,Alo,Bhi,Blo each 128 rows x 32 bf16, padded stride 40
// bf16 (80 B) -> conflict-free ldmatrix (banks 20*r mod 32 distinct).
// ===========================================================================
#define LDSB 80                     // padded row stride in bytes
#define ARR_BYTES (128 * LDSB)      // 10240
#define STG_BYTES (4 * ARR_BYTES)   // 40960
#define SMEM_TOTAL (2 * STG_BYTES)  // 81920

__global__ __launch_bounds__(256) void gemm_bf16x3(
    const __nv_bfloat16* __restrict__ Ahi, const __nv_bfloat16* __restrict__ Alo,
    const __nv_bfloat16* __restrict__ Bhi, const __nv_bfloat16* __restrict__ Blo,
    float* __restrict__ C, int K, int ldc)
{
    extern __shared__ char smem[];
    const uint32_t sb = smem_u32(smem);
    const int tid  = threadIdx.x;
    const int lane = tid & 31, wid = tid >> 5;
    const int wm   = wid & 3, wn = wid >> 2;     // warp tile: 32m x 64n
    const int row0 = blockIdx.y * 128;
    const int col0 = blockIdx.x * 128;

    const __nv_bfloat16* gsrc[4] = {Ahi, Alo, Bhi, Blo};
    const int nchunk = K >> 5;                   // BK=32

    // ---- loader: 512 16B chunks per array, 2 per thread per array --------
    auto issue_stage = [&](int kt, int s) {
        const int k0 = kt << 5;
        const uint32_t sbase = sb + s * STG_BYTES;
#pragma unroll
        for (int a = 0; a < 4; a++) {
            const __nv_bfloat16* g = gsrc[a];
            const int rbase = (a < 2) ? row0 : col0;
#pragma unroll
            for (int i = 0; i < 2; i++) {
                const int c = tid + i * 256;     // 0..511
                const int r = c >> 2, q = c & 3;
                const __nv_bfloat16* src = g + (size_t)(rbase + r) * K + k0 + q * 8;
                const uint32_t dst = sbase + a * ARR_BYTES + r * LDSB + q * 16;
                CP_ASYNC16(dst, src);
            }
        }
        CP_COMMIT();
    };

    float acc[2][8][4];
#pragma unroll
    for (int mt = 0; mt < 2; mt++)
#pragma unroll
        for (int nt = 0; nt < 8; nt++)
#pragma unroll
            for (int r = 0; r < 4; r++) acc[mt][nt][r] = 0.0f;

    // lane-level fragment addressing (byte offsets within an array)
    const int arow = wm * 32 + (lane & 15);
    const int acolb = ((lane >> 4) << 3) * 2;    // 0 or 16 bytes
    const int brow = wn * 64 + (lane & 7) + ((lane >> 4) & 1) * 8;
    const int bcolb = (((lane >> 3) & 1) << 3) * 2;

    auto compute_stage = [&](int s) {
        const uint32_t sbase = sb + s * STG_BYTES;
        const uint32_t sAhi = sbase;
        const uint32_t sAlo = sbase + ARR_BYTES;
        const uint32_t sBhi = sbase + 2 * ARR_BYTES;
        const uint32_t sBlo = sbase + 3 * ARR_BYTES;
#pragma unroll
        for (int h = 0; h < 2; h++) {            // two k16 halves of BK=32
            const int kb = h * 32;               // 16 bf16 = 32 bytes
            uint32_t ah[2][4], al[2][4];
            {
                uint32_t a0 = sAhi + arow * LDSB + acolb + kb;
                LDSM_X4(ah[0][0], ah[0][1], ah[0][2], ah[0][3], a0);
                LDSM_X4(ah[1][0], ah[1][1], ah[1][2], ah[1][3], a0 + 16 * LDSB);
                uint32_t l0 = sAlo + arow * LDSB + acolb + kb;
                LDSM_X4(al[0][0], al[0][1], al[0][2], al[0][3], l0);
                LDSM_X4(al[1][0], al[1][1], al[1][2], al[1][3], l0 + 16 * LDSB);
            }
#pragma unroll
            for (int np = 0; np < 4; np++) {     // pairs of n8 tiles
                uint32_t bh[4], bl[4];
                const uint32_t bo = (brow + np * 16) * LDSB + bcolb + kb;
                LDSM_X4(bh[0], bh[1], bh[2], bh[3], sBhi + bo);
                LDSM_X4(bl[0], bl[1], bl[2], bl[3], sBlo + bo);
#pragma unroll
                for (int mt = 0; mt < 2; mt++) {
#pragma unroll
                    for (int u = 0; u < 2; u++) {
                        float* c = acc[mt][np * 2 + u];
                        MMA_BF16(c, ah[mt], bh[2 * u], bh[2 * u + 1]); // hi*hi
                        MMA_BF16(c, ah[mt], bl[2 * u], bl[2 * u + 1]); // hi*lo
                        MMA_BF16(c, al[mt], bh[2 * u], bh[2 * u + 1]); // lo*hi
                    }
                }
            }
        }
    };

    // ---- pipeline: 2-stage double buffer ---------------------------------
    issue_stage(0, 0);
    if (nchunk > 1) issue_stage(1, 1);

    for (int t = 0; t < nchunk; t++) {
        if (t + 2 < nchunk) { CP_WAIT1(); } else { CP_WAIT0(); }
        __syncthreads();
        compute_stage(t & 1);
        __syncthreads();
        if (t + 2 < nchunk) issue_stage(t + 2, t & 1);
    }

    // ---- epilogue --------------------------------------------------------
#pragma unroll
    for (int mt = 0; mt < 2; mt++) {
#pragma unroll
        for (int nt = 0; nt < 8; nt++) {
            const int r  = row0 + wm * 32 + mt * 16 + (lane >> 2);
            const int cc = col0 + wn * 64 + nt * 8 + (lane & 3) * 2;
            float* p = C + (size_t)r * ldc + cc;
            float2 v0 = make_float2(acc[mt][nt][0], acc[mt][nt][1]);
            float2 v1 = make_float2(acc[mt][nt][2], acc[mt][nt][3]);
            *(float2*)p = v0;
            *(float2*)(p + 8 * ldc) = v1;
        }
    }
}

// ===========================================================================
// fp32 -> bf16 hi/lo split, float4-vectorized
// ===========================================================================
__global__ __launch_bounds__(256) void split_bf16(
    const float* __restrict__ x, __nv_bfloat16* __restrict__ hi,
    __nv_bfloat16* __restrict__ lo, int n4)
{
    int i = blockIdx.x * 256 + threadIdx.x;
    if (i >= n4) return;
    float4 v = ((const float4*)x)[i];
    __nv_bfloat16 h0 = __float2bfloat16_rn(v.x);
    __nv_bfloat16 h1 = __float2bfloat16_rn(v.y);
    __nv_bfloat16 h2 = __float2bfloat16_rn(v.z);
    __nv_bfloat16 h3 = __float2bfloat16_rn(v.w);
    __nv_bfloat16 l0 = __float2bfloat16_rn(v.x - __bfloat162float(h0));
    __nv_bfloat16 l1 = __float2bfloat16_rn(v.y - __bfloat162float(h1));
    __nv_bfloat16 l2 = __float2bfloat16_rn(v.z - __bfloat162float(h2));
    __nv_bfloat16 l3 = __float2bfloat16_rn(v.w - __bfloat162float(h3));
    ((__nv_bfloat162*)hi)[2 * i + 0] = __nv_bfloat162(h0, h1);
    ((__nv_bfloat162*)hi)[2 * i + 1] = __nv_bfloat162(h2, h3);
    ((__nv_bfloat162*)lo)[2 * i + 0] = __nv_bfloat162(l0, l1);
    ((__nv_bfloat162*)lo)[2 * i + 1] = __nv_bfloat162(l2, l3);
}

// ===========================================================================
// SIMT NT GEMM (logits, K=128) — 128x128, BK=8, 8x8 microtile
// ===========================================================================
__global__ __launch_bounds__(256) void gemm_nt(
    const float* __restrict__ A, const float* __restrict__ B, float* __restrict__ C,
    int K, int lda, int ldb, int ldc,
    size_t sAb, size_t sAh, size_t sBb, size_t sBh, size_t sCb, size_t sCh,
    float alpha)
{
    const int z = blockIdx.z;
    const int bb = z >> 4, hh = z & 15;
    A += (size_t)bb * sAb + (size_t)hh * sAh;
    B += (size_t)bb * sBb + (size_t)hh * sBh;
    C += (size_t)bb * sCb + (size_t)hh * sCh;

    __shared__ float As[2][8][128];
    __shared__ float Bs[2][8][128];

    const int tid  = threadIdx.x;
    const int row0 = blockIdx.y * 128;
    const int col0 = blockIdx.x * 128;
    const int lr = tid >> 1;
    const int lk = (tid & 1) << 2;
    const float* Aptr = A + (size_t)(row0 + lr) * lda + lk;
    const float* Bptr = B + (size_t)(col0 + lr) * ldb + lk;
    const int tx = (tid & 15) << 3;
    const int ty = (tid >> 4) << 3;

    float acc[8][8];
#pragma unroll
    for (int i = 0; i < 8; i++)
#pragma unroll
        for (int j = 0; j < 8; j++) acc[i][j] = 0.0f;

    {
        float4 a4 = *(const float4*)(Aptr);
        float4 b4 = *(const float4*)(Bptr);
        As[0][lk + 0][lr] = a4.x; As[0][lk + 1][lr] = a4.y;
        As[0][lk + 2][lr] = a4.z; As[0][lk + 3][lr] = a4.w;
        Bs[0][lk + 0][lr] = b4.x; Bs[0][lk + 1][lr] = b4.y;
        Bs[0][lk + 2][lr] = b4.z; Bs[0][lk + 3][lr] = b4.w;
    }
    __syncthreads();

    int buf = 0;
    for (int k0 = 8; k0 <= K; k0 += 8) {
        float4 na, nb;
        const bool has = (k0 < K);
        if (has) {
            na = *(const float4*)(Aptr + k0);
            nb = *(const float4*)(Bptr + k0);
        }
#pragma unroll
        for (int k = 0; k < 8; k++) {
            float4 a0 = *(const float4*)&As[buf][k][ty];
            float4 a1 = *(const float4*)&As[buf][k][ty + 4];
            float4 b0 = *(const float4*)&Bs[buf][k][tx];
            float4 b1 = *(const float4*)&Bs[buf][k][tx + 4];
            float ar[8] = {a0.x, a0.y, a0.z, a0.w, a1.x, a1.y, a1.z, a1.w};
            float br[8] = {b0.x, b0.y, b0.z, b0.w, b1.x, b1.y, b1.z, b1.w};
#pragma unroll
            for (int i = 0; i < 8; i++)
#pragma unroll
                for (int j = 0; j < 8; j++)
                    acc[i][j] = fmaf(ar[i], br[j], acc[i][j]);
        }
        if (has) {
            const int nb_ = buf ^ 1;
            As[nb_][lk + 0][lr] = na.x; As[nb_][lk + 1][lr] = na.y;
            As[nb_][lk + 2][lr] = na.z; As[nb_][lk + 3][lr] = na.w;
            Bs[nb_][lk + 0][lr] = nb.x; Bs[nb_][lk + 1][lr] = nb.y;
            Bs[nb_][lk + 2][lr] = nb.z; Bs[nb_][lk + 3][lr] = nb.w;
            __syncthreads();
            buf = nb_;
        }
    }

#pragma unroll
    for (int i = 0; i < 8; i++) {
        float* crow = C + (size_t)(row0 + ty + i) * ldc + col0 + tx;
        float4 o0, o1;
        o0.x = acc[i][0] * alpha; o0.y = acc[i][1] * alpha;
        o0.z = acc[i][2] * alpha; o0.w = acc[i][3] * alpha;
        o1.x = acc[i][4] * alpha; o1.y = acc[i][5] * alpha;
        o1.z = acc[i][6] * alpha; o1.w = acc[i][7] * alpha;
        *(float4*)(crow)     = o0;
        *(float4*)(crow + 4) = o1;
    }
}

// ===========================================================================
// SIMT NN GEMM (P @ V)
// ===========================================================================
__global__ __launch_bounds__(256) void gemm_nn(
    const float* __restrict__ A, const float* __restrict__ B, float* __restrict__ C,
    int K, int lda, int ldb, int ldc,
    size_t sAb, size_t sAh, size_t sBb, size_t sBh, size_t sCb, size_t sCh,
    float alpha)
{
    const int z = blockIdx.z;
    const int bb = z >> 4, hh = z & 15;
    A += (size_t)bb * sAb + (size_t)hh * sAh;
    B += (size_t)bb * sBb + (size_t)hh * sBh;
    C += (size_t)bb * sCb + (size_t)hh * sCh;

    __shared__ float As[2][8][128];
    __shared__ float Bs[2][8][128];

    const int tid  = threadIdx.x;
    const int row0 = blockIdx.y * 128;
    const int col0 = blockIdx.x * 128;
    const int lr = tid >> 1;
    const int lk = (tid & 1) << 2;
    const float* Aptr = A + (size_t)(row0 + lr) * lda + lk;
    const int kr = tid >> 5;
    const int ln = (tid & 31) << 2;
    const float* Bptr = B + (size_t)kr * ldb + col0 + ln;
    const int tx = (tid & 15) << 3;
    const int ty = (tid >> 4) << 3;

    float acc[8][8];
#pragma unroll
    for (int i = 0; i < 8; i++)
#pragma unroll
        for (int j = 0; j < 8; j++) acc[i][j] = 0.0f;

    {
        float4 a4 = *(const float4*)(Aptr);
        float4 b4 = *(const float4*)(Bptr);
        As[0][lk + 0][lr] = a4.x; As[0][lk + 1][lr] = a4.y;
        As[0][lk + 2][lr] = a4.z; As[0][lk + 3][lr] = a4.w;
        *(float4*)&Bs[0][kr][ln] = b4;
    }
    __syncthreads();

    int buf = 0;
    for (int k0 = 8; k0 <= K; k0 += 8) {
        float4 na, nb;
        const bool has = (k0 < K);
        if (has) {
            na = *(const float4*)(Aptr + k0);
            nb = *(const float4*)(Bptr + (size_t)k0 * ldb);
        }
#pragma unroll
        for (int k = 0; k < 8; k++) {
            float4 a0 = *(const float4*)&As[buf][k][ty];
            float4 a1 = *(const float4*)&As[buf][k][ty + 4];
            float4 b0 = *(const float4*)&Bs[buf][k][tx];
            float4 b1 = *(const float4*)&Bs[buf][k][tx + 4];
            float ar[8] = {a0.x, a0.y, a0.z, a0.w, a1.x, a1.y, a1.z, a1.w};
            float br[8] = {b0.x, b0.y, b0.z, b0.w, b1.x, b1.y, b1.z, b1.w};
#pragma unroll
            for (int i = 0; i < 8; i++)
#pragma unroll
                for (int j = 0; j < 8; j++)
                    acc[i][j] = fmaf(ar[i], br[j], acc[i][j]);
        }
        if (has) {
            const int nb_ = buf ^ 1;
            As[nb_][lk + 0][lr] = na.x; As[nb_][lk + 1][lr] = na.y;
            As[nb_][lk + 2][lr] = na.z; As[nb_][lk + 3][lr] = na.w;
            *(float4*)&Bs[nb_][kr][ln] = nb;
            __syncthreads();
            buf = nb_;
        }
    }

#pragma unroll
    for (int i = 0; i < 8; i++) {
        float* crow = C + (size_t)(row0 + ty + i) * ldc + col0 + tx;
        float4 o0, o1;
        o0.x = acc[i][0] * alpha; o0.y = acc[i][1] * alpha;
        o0.z = acc[i][2] * alpha; o0.w = acc[i][3] * alpha;
        o1.x = acc[i][4] * alpha; o1.y = acc[i][5] * alpha;
        o1.z = acc[i][6] * alpha; o1.w = acc[i][7] * alpha;
        *(float4*)(crow)     = o0;
        *(float4*)(crow + 4) = o1;
    }
}

// ===========================================================================
// Row softmax in place (row length 2048, one 256-thread block per row)
// ===========================================================================
__global__ __launch_bounds__(256) void softmax_rows(float* __restrict__ X)
{
    float4* x4 = (float4*)(X + blockIdx.x * (size_t)S_LEN);
    const int tid = threadIdx.x;
    const int lane = tid & 31, warp = tid >> 5;
    __shared__ float red[8];

    float4 u = x4[tid];
    float4 w = x4[tid + 256];

    float m = fmaxf(fmaxf(fmaxf(u.x, u.y), fmaxf(u.z, u.w)),
                    fmaxf(fmaxf(w.x, w.y), fmaxf(w.z, w.w)));
#pragma unroll
    for (int o = 16; o > 0; o >>= 1) m = fmaxf(m, __shfl_xor_sync(0xffffffffu, m, o));
    if (lane == 0) red[warp] = m;
    __syncthreads();
    m = red[0];
#pragma unroll
    for (int i = 1; i < 8; i++) m = fmaxf(m, red[i]);
    __syncthreads();

    u.x = __expf(u.x - m); u.y = __expf(u.y - m);
    u.z = __expf(u.z - m); u.w = __expf(u.w - m);
    w.x = __expf(w.x - m); w.y = __expf(w.y - m);
    w.z = __expf(w.z - m); w.w = __expf(w.w - m);

    float s = (u.x + u.y) + (u.z + u.w) + (w.x + w.y) + (w.z + w.w);
#pragma unroll
    for (int o = 16; o > 0; o >>= 1) s += __shfl_xor_sync(0xffffffffu, s, o);
    if (lane == 0) red[warp] = s;
    __syncthreads();
    s = red[0];
#pragma unroll
    for (int i = 1; i < 8; i++) s += red[i];
    const float inv = 1.0f / s;

    u.x *= inv; u.y *= inv; u.z *= inv; u.w *= inv;
    w.x *= inv; w.y *= inv; w.z *= inv; w.w *= inv;
    x4[tid] = u;
    x4[tid + 256] = w;
}

// ---------------------------------------------------------------------------
extern "C" void kernel_launch(void* const* d_in, const int* in_sizes, int n_in,
                              void* d_out, int out_size)
{
    const float* q   = (const float*)d_in[0];
    const float* k   = (const float*)d_in[1];
    const float* v   = (const float*)d_in[2];
    const float* w_q = (const float*)d_in[3];
    const float* w_k = (const float*)d_in[4];
    const float* w_v = (const float*)d_in[5];
    const float* w_o = (const float*)d_in[6];
    float* out = (float*)d_out;

    float *gq, *gk, *gv, *gattn, *glog;
    __nv_bfloat16 *ahi, *alo, *whi, *wlo;
    cudaGetSymbolAddress((void**)&gq, g_q);
    cudaGetSymbolAddress((void**)&gk, g_k);
    cudaGetSymbolAddress((void**)&gv, g_v);
    cudaGetSymbolAddress((void**)&gattn, g_attn);
    cudaGetSymbolAddress((void**)&glog, g_logits);
    cudaGetSymbolAddress((void**)&ahi, g_act_hi);
    cudaGetSymbolAddress((void**)&alo, g_act_lo);
    cudaGetSymbolAddress((void**)&whi, g_w_hi);
    cudaGetSymbolAddress((void**)&wlo, g_w_lo);

    cudaFuncSetAttribute(gemm_bf16x3, cudaFuncAttributeMaxDynamicSharedMemorySize, SMEM_TOTAL);

    const int M_rows = NBATCH * S_LEN;                 // 8192
    const size_t SD  = (size_t)S_LEN * DMODEL;
    const size_t SS  = (size_t)S_LEN * S_LEN;
    const float inv_sqrt_dk = 1.0f / sqrtf((float)DK);

    const int nact4 = (int)((size_t)M_rows * DMODEL / 4);
    const int nw4   = (int)((size_t)DMODEL * DMODEL / 4);
    dim3 blk(256);
    dim3 grid_tc(DMODEL / 128, M_rows / 128, 1);       // 16 x 64

    // 1) Projections via mma.sync bf16x3
    split_bf16<<<(nact4 + 255) / 256, blk>>>(q, ahi, alo, nact4);
    split_bf16<<<(nw4 + 255) / 256, blk>>>(w_q, whi, wlo, nw4);
    gemm_bf16x3<<<grid_tc, blk, SMEM_TOTAL>>>(ahi, alo, whi, wlo, gq, DMODEL, DMODEL);

    split_bf16<<<(nact4 + 255) / 256, blk>>>(k, ahi, alo, nact4);
    split_bf16<<<(nw4 + 255) / 256, blk>>>(w_k, whi, wlo, nw4);
    gemm_bf16x3<<<grid_tc, blk, SMEM_TOTAL>>>(ahi, alo, whi, wlo, gk, DMODEL, DMODEL);

    split_bf16<<<(nact4 + 255) / 256, blk>>>(v, ahi, alo, nact4);
    split_bf16<<<(nw4 + 255) / 256, blk>>>(w_v, whi, wlo, nw4);
    gemm_bf16x3<<<grid_tc, blk, SMEM_TOTAL>>>(ahi, alo, whi, wlo, gv, DMODEL, DMODEL);

    // 2) Logits: per (b,h), Qh @ Kh^T / sqrt(Dk)  (SIMT, K=128)
    {
        dim3 grid(S_LEN / 128, S_LEN / 128, NBATCH * NHEADS);
        gemm_nt<<<grid, blk>>>(gq, gk, glog, DK, DMODEL, DMODEL, S_LEN,
                               SD, (size_t)DK, SD, (size_t)DK,
                               (size_t)NHEADS * SS, SS, inv_sqrt_dk);
    }

    // 3) Softmax
    softmax_rows<<<NBATCH * NHEADS * S_LEN, blk>>>(glog);

    // 4) Attn = P @ Vh (SIMT NN), head-interleaved output
    {
        dim3 grid(DK / 128, S_LEN / 128, NBATCH * NHEADS);
        gemm_nn<<<grid, blk>>>(glog, gv, gattn, S_LEN, S_LEN, DMODEL, DMODEL,
                               (size_t)NHEADS * SS, SS,
                               SD, (size_t)DK, SD, (size_t)DK, 1.0f);
    }

    // 5) Output projection via mma.sync bf16x3
    split_bf16<<<(nact4 + 255) / 256, blk>>>(gattn, ahi, alo, nact4);
    split_bf16<<<(nw4 + 255) / 256, blk>>>(w_o, whi, wlo, nw4);
    gemm_bf16x3<<<grid_tc, blk, SMEM_TOTAL>>>(ahi, alo, whi, wlo, out, DMODEL, DMODEL);
}

// round 6
// speedup vs baseline: 3.0404x; 1.4308x over previous
#include <cuda_runtime.h>
#include <cuda_bf16.h>
#include <math.h>
#include <stdint.h>

#define S_LEN   2048
#define DMODEL  2048
#define NHEADS  16
#define DK      128
#define NBATCH  4

// ---------------- static device scratch (no allocations allowed) ----------
__device__ float g_logits[(size_t)NBATCH * NHEADS * S_LEN * S_LEN]; // 1.07 GB
__device__ __nv_bfloat16 g_qhi[(size_t)NBATCH * S_LEN * DMODEL];
__device__ __nv_bfloat16 g_qlo[(size_t)NBATCH * S_LEN * DMODEL];
__device__ __nv_bfloat16 g_khi[(size_t)NBATCH * S_LEN * DMODEL];
__device__ __nv_bfloat16 g_klo[(size_t)NBATCH * S_LEN * DMODEL];
__device__ __nv_bfloat16 g_vhi[(size_t)NBATCH * S_LEN * DMODEL];
__device__ __nv_bfloat16 g_vlo[(size_t)NBATCH * S_LEN * DMODEL];
__device__ __nv_bfloat16 g_phi[(size_t)NBATCH * NHEADS * S_LEN * S_LEN]; // 536 MB
__device__ __nv_bfloat16 g_plo[(size_t)NBATCH * NHEADS * S_LEN * S_LEN]; // 536 MB
__device__ __nv_bfloat16 g_athi[(size_t)NBATCH * S_LEN * DMODEL];
__device__ __nv_bfloat16 g_atlo[(size_t)NBATCH * S_LEN * DMODEL];
__device__ __nv_bfloat16 g_act_hi[(size_t)NBATCH * S_LEN * DMODEL];
__device__ __nv_bfloat16 g_act_lo[(size_t)NBATCH * S_LEN * DMODEL];
__device__ __nv_bfloat16 g_w_hi[(size_t)DMODEL * DMODEL];
__device__ __nv_bfloat16 g_w_lo[(size_t)DMODEL * DMODEL];

// ======================= PTX helpers =======================================
__device__ __forceinline__ uint32_t smem_u32(const void* p) {
    uint32_t a;
    asm("{ .reg .u64 t; cvta.to.shared.u64 t, %1; cvt.u32.u64 %0, t; }" : "=r"(a) : "l"(p));
    return a;
}
#define CP_ASYNC16(dst, src) asm volatile("cp.async.cg.shared.global [%0], [%1], 16;" :: "r"(dst), "l"(src))
#define CP_COMMIT()          asm volatile("cp.async.commit_group;" ::: "memory")
#define CP_WAIT0()           asm volatile("cp.async.wait_group 0;" ::: "memory")
#define CP_WAIT1()           asm volatile("cp.async.wait_group 1;" ::: "memory")

#define LDSM_X4(r0, r1, r2, r3, addr) \
    asm volatile("ldmatrix.sync.aligned.m8n8.x4.shared.b16 {%0,%1,%2,%3}, [%4];" \
        : "=r"(r0), "=r"(r1), "=r"(r2), "=r"(r3) : "r"(addr))
#define LDSM_X4_T(r0, r1, r2, r3, addr) \
    asm volatile("ldmatrix.sync.aligned.m8n8.x4.trans.shared.b16 {%0,%1,%2,%3}, [%4];" \
        : "=r"(r0), "=r"(r1), "=r"(r2), "=r"(r3) : "r"(addr))

#define MMA_BF16(c, a, b0, b1) \
    asm volatile("mma.sync.aligned.m16n8k16.row.col.f32.bf16.bf16.f32 " \
        "{%0,%1,%2,%3},{%4,%5,%6,%7},{%8,%9},{%0,%1,%2,%3};" \
        : "+f"((c)[0]), "+f"((c)[1]), "+f"((c)[2]), "+f"((c)[3]) \
        : "r"((a)[0]), "r"((a)[1]), "r"((a)[2]), "r"((a)[3]), "r"(b0), "r"(b1))

__device__ __forceinline__ void split2(float x, __nv_bfloat16& h, __nv_bfloat16& l) {
    h = __float2bfloat16_rn(x);
    l = __float2bfloat16_rn(x - __bfloat162float(h));
}

// ===========================================================================
// bf16x3 NT GEMM via mma.sync: C[m,n] = alpha * sum_k A[m,k]*B[n,k]
// Block 128x128, BK=32, 256 threads (8 warps, 4m x 2n), double buffer.
// OUTMODE 0: fp32 C.  OUTMODE 1: bf16 hi/lo C pair.
// ===========================================================================
#define LDSB 80
#define ARR_BYTES (128 * LDSB)      // 10240
#define STG_BYTES (4 * ARR_BYTES)   // 40960
#define NT_SMEM (2 * STG_BYTES)     // 81920

template<int OUTMODE>
__global__ __launch_bounds__(256) void gemm_nt_tc(
    const __nv_bfloat16* __restrict__ Ahi, const __nv_bfloat16* __restrict__ Alo,
    const __nv_bfloat16* __restrict__ Bhi, const __nv_bfloat16* __restrict__ Blo,
    float* __restrict__ Cf, __nv_bfloat16* __restrict__ Chi, __nv_bfloat16* __restrict__ Clo,
    int K, int lda, int ldb, int ldc,
    size_t sAb, size_t sAh, size_t sBb, size_t sBh, size_t sCb, size_t sCh,
    float alpha)
{
    extern __shared__ char smem[];
    const uint32_t sb = smem_u32(smem);
    const int tid  = threadIdx.x;
    const int lane = tid & 31, wid = tid >> 5;
    const int wm   = wid & 3, wn = wid >> 2;
    const int row0 = blockIdx.y * 128;
    const int col0 = blockIdx.x * 128;

    const int z = blockIdx.z;
    const int bb = z >> 4, hh = z & 15;
    Ahi += (size_t)bb * sAb + (size_t)hh * sAh;
    Alo += (size_t)bb * sAb + (size_t)hh * sAh;
    Bhi += (size_t)bb * sBb + (size_t)hh * sBh;
    Blo += (size_t)bb * sBb + (size_t)hh * sBh;
    const size_t coff = (size_t)bb * sCb + (size_t)hh * sCh;

    const __nv_bfloat16* gsrc[4] = {Ahi, Alo, Bhi, Blo};
    const int nchunk = K >> 5;

    auto issue_stage = [&](int kt, int s) {
        const int k0 = kt << 5;
        const uint32_t sbase = sb + s * STG_BYTES;
#pragma unroll
        for (int a = 0; a < 4; a++) {
            const __nv_bfloat16* g = gsrc[a];
            const int rbase = (a < 2) ? row0 : col0;
            const int ld    = (a < 2) ? lda : ldb;
#pragma unroll
            for (int i = 0; i < 2; i++) {
                const int c = tid + i * 256;
                const int r = c >> 2, q = c & 3;
                const __nv_bfloat16* src = g + (size_t)(rbase + r) * ld + k0 + q * 8;
                const uint32_t dst = sbase + a * ARR_BYTES + r * LDSB + q * 16;
                CP_ASYNC16(dst, src);
            }
        }
        CP_COMMIT();
    };

    float acc[2][8][4];
#pragma unroll
    for (int mt = 0; mt < 2; mt++)
#pragma unroll
        for (int nt = 0; nt < 8; nt++)
#pragma unroll
            for (int r = 0; r < 4; r++) acc[mt][nt][r] = 0.0f;

    const int arow  = wm * 32 + (lane & 15);
    const int acolb = ((lane >> 4) << 3) * 2;
    const int brow  = wn * 64 + (lane & 7) + ((lane >> 4) & 1) * 8;
    const int bcolb = (((lane >> 3) & 1) << 3) * 2;

    auto compute_stage = [&](int s) {
        const uint32_t sbase = sb + s * STG_BYTES;
        const uint32_t sAhi = sbase;
        const uint32_t sAlo = sbase + ARR_BYTES;
        const uint32_t sBhi = sbase + 2 * ARR_BYTES;
        const uint32_t sBlo = sbase + 3 * ARR_BYTES;
#pragma unroll
        for (int h = 0; h < 2; h++) {
            const int kb = h * 32;
            uint32_t ah[2][4], al[2][4];
            {
                uint32_t a0 = sAhi + arow * LDSB + acolb + kb;
                LDSM_X4(ah[0][0], ah[0][1], ah[0][2], ah[0][3], a0);
                LDSM_X4(ah[1][0], ah[1][1], ah[1][2], ah[1][3], a0 + 16 * LDSB);
                uint32_t l0 = sAlo + arow * LDSB + acolb + kb;
                LDSM_X4(al[0][0], al[0][1], al[0][2], al[0][3], l0);
                LDSM_X4(al[1][0], al[1][1], al[1][2], al[1][3], l0 + 16 * LDSB);
            }
#pragma unroll
            for (int np = 0; np < 4; np++) {
                uint32_t bh[4], bl[4];
                const uint32_t bo = (brow + np * 16) * LDSB + bcolb + kb;
                LDSM_X4(bh[0], bh[1], bh[2], bh[3], sBhi + bo);
                LDSM_X4(bl[0], bl[1], bl[2], bl[3], sBlo + bo);
#pragma unroll
                for (int mt = 0; mt < 2; mt++) {
#pragma unroll
                    for (int u = 0; u < 2; u++) {
                        float* c = acc[mt][np * 2 + u];
                        MMA_BF16(c, ah[mt], bh[2 * u], bh[2 * u + 1]);
                        MMA_BF16(c, ah[mt], bl[2 * u], bl[2 * u + 1]);
                        MMA_BF16(c, al[mt], bh[2 * u], bh[2 * u + 1]);
                    }
                }
            }
        }
    };

    issue_stage(0, 0);
    if (nchunk > 1) issue_stage(1, 1);
    for (int t = 0; t < nchunk; t++) {
        if (t + 2 < nchunk) { CP_WAIT1(); } else { CP_WAIT0(); }
        __syncthreads();
        compute_stage(t & 1);
        __syncthreads();
        if (t + 2 < nchunk) issue_stage(t + 2, t & 1);
    }

#pragma unroll
    for (int mt = 0; mt < 2; mt++) {
#pragma unroll
        for (int nt = 0; nt < 8; nt++) {
            const int r  = row0 + wm * 32 + mt * 16 + (lane >> 2);
            const int cc = col0 + wn * 64 + nt * 8 + (lane & 3) * 2;
            if (OUTMODE == 0) {
                float* p = Cf + coff + (size_t)r * ldc + cc;
                *(float2*)p = make_float2(acc[mt][nt][0] * alpha, acc[mt][nt][1] * alpha);
                *(float2*)(p + 8 * ldc) = make_float2(acc[mt][nt][2] * alpha, acc[mt][nt][3] * alpha);
            } else {
                __nv_bfloat16 h0, h1, l0, l1;
                split2(acc[mt][nt][0] * alpha, h0, l0);
                split2(acc[mt][nt][1] * alpha, h1, l1);
                *(__nv_bfloat162*)(Chi + coff + (size_t)r * ldc + cc) = __nv_bfloat162(h0, h1);
                *(__nv_bfloat162*)(Clo + coff + (size_t)r * ldc + cc) = __nv_bfloat162(l0, l1);
                split2(acc[mt][nt][2] * alpha, h0, l0);
                split2(acc[mt][nt][3] * alpha, h1, l1);
                *(__nv_bfloat162*)(Chi + coff + (size_t)(r + 8) * ldc + cc) = __nv_bfloat162(h0, h1);
                *(__nv_bfloat162*)(Clo + coff + (size_t)(r + 8) * ldc + cc) = __nv_bfloat162(l0, l1);
            }
        }
    }
}

// ===========================================================================
// bf16x3 NN GEMM (P @ V): C[m,n] = sum_k A[m,k]*B[k,n]; B row-major,
// loaded with ldmatrix.trans. Output bf16 hi/lo. N tile = 128 (full head).
// B tile: 32 k-rows x 128 n-cols bf16 = 256 B/row, padded to 272 B.
// ===========================================================================
#define PV_B_LDSB 272
#define PV_B_BYTES (32 * PV_B_LDSB)                  // 8704
#define PV_STG (2 * ARR_BYTES + 2 * PV_B_BYTES)      // 37888
#define PV_SMEM (2 * PV_STG)                         // 75776

__global__ __launch_bounds__(256) void gemm_nn_tc(
    const __nv_bfloat16* __restrict__ Ahi, const __nv_bfloat16* __restrict__ Alo,
    const __nv_bfloat16* __restrict__ Bhi, const __nv_bfloat16* __restrict__ Blo,
    __nv_bfloat16* __restrict__ Chi, __nv_bfloat16* __restrict__ Clo,
    int K, int lda, int ldb, int ldc,
    size_t sAb, size_t sAh, size_t sBb, size_t sBh, size_t sCb, size_t sCh)
{
    extern __shared__ char smem[];
    const uint32_t sb = smem_u32(smem);
    const int tid  = threadIdx.x;
    const int lane = tid & 31, wid = tid >> 5;
    const int wm   = wid & 3, wn = wid >> 2;
    const int row0 = blockIdx.y * 128;
    const int col0 = blockIdx.x * 128;

    const int z = blockIdx.z;
    const int bb = z >> 4, hh = z & 15;
    Ahi += (size_t)bb * sAb + (size_t)hh * sAh;
    Alo += (size_t)bb * sAb + (size_t)hh * sAh;
    Bhi += (size_t)bb * sBb + (size_t)hh * sBh;
    Blo += (size_t)bb * sBb + (size_t)hh * sBh;
    const size_t coff = (size_t)bb * sCb + (size_t)hh * sCh;

    const int nchunk = K >> 5;

    auto issue_stage = [&](int kt, int s) {
        const int k0 = kt << 5;
        const uint32_t sbase = sb + s * PV_STG;
        // A: 2 arrays x 512 chunks (128 rows x 4 x 16B)
#pragma unroll
        for (int a = 0; a < 2; a++) {
            const __nv_bfloat16* g = (a == 0) ? Ahi : Alo;
#pragma unroll
            for (int i = 0; i < 2; i++) {
                const int c = tid + i * 256;
                const int r = c >> 2, q = c & 3;
                const __nv_bfloat16* src = g + (size_t)(row0 + r) * lda + k0 + q * 8;
                const uint32_t dst = sbase + a * ARR_BYTES + r * LDSB + q * 16;
                CP_ASYNC16(dst, src);
            }
        }
        // B: 2 arrays x 512 chunks (32 k-rows x 16 x 16B = 128 n cols)
#pragma unroll
        for (int a = 0; a < 2; a++) {
            const __nv_bfloat16* g = (a == 0) ? Bhi : Blo;
#pragma unroll
            for (int i = 0; i < 2; i++) {
                const int c = tid + i * 256;
                const int r = c >> 4, q = c & 15;
                const __nv_bfloat16* src = g + (size_t)(k0 + r) * ldb + col0 + q * 8;
                const uint32_t dst = sbase + 2 * ARR_BYTES + a * PV_B_BYTES + r * PV_B_LDSB + q * 16;
                CP_ASYNC16(dst, src);
            }
        }
        CP_COMMIT();
    };

    float acc[2][8][4];
#pragma unroll
    for (int mt = 0; mt < 2; mt++)
#pragma unroll
        for (int nt = 0; nt < 8; nt++)
#pragma unroll
            for (int r = 0; r < 4; r++) acc[mt][nt][r] = 0.0f;

    const int arow  = wm * 32 + (lane & 15);
    const int acolb = ((lane >> 4) << 3) * 2;
    // trans-B lane addressing: k-row within 16-block, n col offset 0/8
    const int btr = (lane & 7) + ((lane >> 3) & 1) * 8;
    const int btc = ((lane >> 4) & 1) << 3;

    auto compute_stage = [&](int s) {
        const uint32_t sbase = sb + s * PV_STG;
        const uint32_t sAhi = sbase;
        const uint32_t sAlo = sbase + ARR_BYTES;
        const uint32_t sBhi = sbase + 2 * ARR_BYTES;
        const uint32_t sBlo = sbase + 2 * ARR_BYTES + PV_B_BYTES;
#pragma unroll
        for (int h = 0; h < 2; h++) {
            const int kb = h * 32;
            uint32_t ah[2][4], al[2][4];
            {
                uint32_t a0 = sAhi + arow * LDSB + acolb + kb;
                LDSM_X4(ah[0][0], ah[0][1], ah[0][2], ah[0][3], a0);
                LDSM_X4(ah[1][0], ah[1][1], ah[1][2], ah[1][3], a0 + 16 * LDSB);
                uint32_t l0 = sAlo + arow * LDSB + acolb + kb;
                LDSM_X4(al[0][0], al[0][1], al[0][2], al[0][3], l0);
                LDSM_X4(al[1][0], al[1][1], al[1][2], al[1][3], l0 + 16 * LDSB);
            }
#pragma unroll
            for (int np = 0; np < 4; np++) {
                const int n0 = wn * 64 + np * 16;
                const uint32_t bo = (uint32_t)(h * 16 + btr) * PV_B_LDSB + (n0 + btc) * 2;
                uint32_t bh[4], bl[4];
                LDSM_X4_T(bh[0], bh[1], bh[2], bh[3], sBhi + bo);
                LDSM_X4_T(bl[0], bl[1], bl[2], bl[3], sBlo + bo);
#pragma unroll
                for (int mt = 0; mt < 2; mt++) {
#pragma unroll
                    for (int u = 0; u < 2; u++) {
                        float* c = acc[mt][np * 2 + u];
                        MMA_BF16(c, ah[mt], bh[2 * u], bh[2 * u + 1]);
                        MMA_BF16(c, ah[mt], bl[2 * u], bl[2 * u + 1]);
                        MMA_BF16(c, al[mt], bh[2 * u], bh[2 * u + 1]);
                    }
                }
            }
        }
    };

    issue_stage(0, 0);
    if (nchunk > 1) issue_stage(1, 1);
    for (int t = 0; t < nchunk; t++) {
        if (t + 2 < nchunk) { CP_WAIT1(); } else { CP_WAIT0(); }
        __syncthreads();
        compute_stage(t & 1);
        __syncthreads();
        if (t + 2 < nchunk) issue_stage(t + 2, t & 1);
    }

#pragma unroll
    for (int mt = 0; mt < 2; mt++) {
#pragma unroll
        for (int nt = 0; nt < 8; nt++) {
            const int r  = row0 + wm * 32 + mt * 16 + (lane >> 2);
            const int cc = col0 + wn * 64 + nt * 8 + (lane & 3) * 2;
            __nv_bfloat16 h0, h1, l0, l1;
            split2(acc[mt][nt][0], h0, l0);
            split2(acc[mt][nt][1], h1, l1);
            *(__nv_bfloat162*)(Chi + coff + (size_t)r * ldc + cc) = __nv_bfloat162(h0, h1);
            *(__nv_bfloat162*)(Clo + coff + (size_t)r * ldc + cc) = __nv_bfloat162(l0, l1);
            split2(acc[mt][nt][2], h0, l0);
            split2(acc[mt][nt][3], h1, l1);
            *(__nv_bfloat162*)(Chi + coff + (size_t)(r + 8) * ldc + cc) = __nv_bfloat162(h0, h1);
            *(__nv_bfloat162*)(Clo + coff + (size_t)(r + 8) * ldc + cc) = __nv_bfloat162(l0, l1);
        }
    }
}

// ===========================================================================
// fp32 -> bf16 hi/lo split (inputs and weights)
// ===========================================================================
__global__ __launch_bounds__(256) void split_bf16(
    const float* __restrict__ x, __nv_bfloat16* __restrict__ hi,
    __nv_bfloat16* __restrict__ lo, int n4)
{
    int i = blockIdx.x * 256 + threadIdx.x;
    if (i >= n4) return;
    float4 v = ((const float4*)x)[i];
    __nv_bfloat16 h0, h1, h2, h3, l0, l1, l2, l3;
    split2(v.x, h0, l0); split2(v.y, h1, l1);
    split2(v.z, h2, l2); split2(v.w, h3, l3);
    ((__nv_bfloat162*)hi)[2 * i + 0] = __nv_bfloat162(h0, h1);
    ((__nv_bfloat162*)hi)[2 * i + 1] = __nv_bfloat162(h2, h3);
    ((__nv_bfloat162*)lo)[2 * i + 0] = __nv_bfloat162(l0, l1);
    ((__nv_bfloat162*)lo)[2 * i + 1] = __nv_bfloat162(l2, l3);
}

// ===========================================================================
// Softmax: reads fp32 logits row (2048), writes P as bf16 hi/lo.
// ===========================================================================
__global__ __launch_bounds__(256) void softmax_split(
    const float* __restrict__ X, __nv_bfloat16* __restrict__ Phi,
    __nv_bfloat16* __restrict__ Plo)
{
    const size_t row = blockIdx.x;
    const float4* x4 = (const float4*)(X + row * (size_t)S_LEN);
    const int tid = threadIdx.x;
    const int lane = tid & 31, warp = tid >> 5;
    __shared__ float red[8];

    float4 u = x4[tid];
    float4 w = x4[tid + 256];

    float m = fmaxf(fmaxf(fmaxf(u.x, u.y), fmaxf(u.z, u.w)),
                    fmaxf(fmaxf(w.x, w.y), fmaxf(w.z, w.w)));
#pragma unroll
    for (int o = 16; o > 0; o >>= 1) m = fmaxf(m, __shfl_xor_sync(0xffffffffu, m, o));
    if (lane == 0) red[warp] = m;
    __syncthreads();
    m = red[0];
#pragma unroll
    for (int i = 1; i < 8; i++) m = fmaxf(m, red[i]);
    __syncthreads();

    u.x = __expf(u.x - m); u.y = __expf(u.y - m);
    u.z = __expf(u.z - m); u.w = __expf(u.w - m);
    w.x = __expf(w.x - m); w.y = __expf(w.y - m);
    w.z = __expf(w.z - m); w.w = __expf(w.w - m);

    float s = (u.x + u.y) + (u.z + u.w) + (w.x + w.y) + (w.z + w.w);
#pragma unroll
    for (int o = 16; o > 0; o >>= 1) s += __shfl_xor_sync(0xffffffffu, s, o);
    if (lane == 0) red[warp] = s;
    __syncthreads();
    s = red[0];
#pragma unroll
    for (int i = 1; i < 8; i++) s += red[i];
    const float inv = 1.0f / s;

    u.x *= inv; u.y *= inv; u.z *= inv; u.w *= inv;
    w.x *= inv; w.y *= inv; w.z *= inv; w.w *= inv;

    __nv_bfloat162* ph = (__nv_bfloat162*)(Phi + row * (size_t)S_LEN);
    __nv_bfloat162* pl = (__nv_bfloat162*)(Plo + row * (size_t)S_LEN);
    __nv_bfloat16 h0, h1, l0, l1;
    split2(u.x, h0, l0); split2(u.y, h1, l1);
    ph[2 * tid] = __nv_bfloat162(h0, h1); pl[2 * tid] = __nv_bfloat162(l0, l1);
    split2(u.z, h0, l0); split2(u.w, h1, l1);
    ph[2 * tid + 1] = __nv_bfloat162(h0, h1); pl[2 * tid + 1] = __nv_bfloat162(l0, l1);
    split2(w.x, h0, l0); split2(w.y, h1, l1);
    ph[2 * tid + 512] = __nv_bfloat162(h0, h1); pl[2 * tid + 512] = __nv_bfloat162(l0, l1);
    split2(w.z, h0, l0); split2(w.w, h1, l1);
    ph[2 * tid + 513] = __nv_bfloat162(h0, h1); pl[2 * tid + 513] = __nv_bfloat162(l0, l1);
}

// ---------------------------------------------------------------------------
extern "C" void kernel_launch(void* const* d_in, const int* in_sizes, int n_in,
                              void* d_out, int out_size)
{
    const float* q   = (const float*)d_in[0];
    const float* k   = (const float*)d_in[1];
    const float* v   = (const float*)d_in[2];
    const float* w_q = (const float*)d_in[3];
    const float* w_k = (const float*)d_in[4];
    const float* w_v = (const float*)d_in[5];
    const float* w_o = (const float*)d_in[6];
    float* out = (float*)d_out;

    float* glog;
    __nv_bfloat16 *qhi, *qlo, *khi, *klo, *vhi, *vlo, *phi, *plo, *athi, *atlo;
    __nv_bfloat16 *ahi, *alo, *whi, *wlo;
    cudaGetSymbolAddress((void**)&glog, g_logits);
    cudaGetSymbolAddress((void**)&qhi, g_qhi);  cudaGetSymbolAddress((void**)&qlo, g_qlo);
    cudaGetSymbolAddress((void**)&khi, g_khi);  cudaGetSymbolAddress((void**)&klo, g_klo);
    cudaGetSymbolAddress((void**)&vhi, g_vhi);  cudaGetSymbolAddress((void**)&vlo, g_vlo);
    cudaGetSymbolAddress((void**)&phi, g_phi);  cudaGetSymbolAddress((void**)&plo, g_plo);
    cudaGetSymbolAddress((void**)&athi, g_athi); cudaGetSymbolAddress((void**)&atlo, g_atlo);
    cudaGetSymbolAddress((void**)&ahi, g_act_hi); cudaGetSymbolAddress((void**)&alo, g_act_lo);
    cudaGetSymbolAddress((void**)&whi, g_w_hi);  cudaGetSymbolAddress((void**)&wlo, g_w_lo);

    cudaFuncSetAttribute(gemm_nt_tc<0>, cudaFuncAttributeMaxDynamicSharedMemorySize, NT_SMEM);
    cudaFuncSetAttribute(gemm_nt_tc<1>, cudaFuncAttributeMaxDynamicSharedMemorySize, NT_SMEM);
    cudaFuncSetAttribute(gemm_nn_tc, cudaFuncAttributeMaxDynamicSharedMemorySize, PV_SMEM);

    const int M_rows = NBATCH * S_LEN;
    const size_t SD  = (size_t)S_LEN * DMODEL;
    const size_t SS  = (size_t)S_LEN * S_LEN;
    const float inv_sqrt_dk = 1.0f / sqrtf((float)DK);

    const int nact4 = (int)((size_t)M_rows * DMODEL / 4);
    const int nw4   = (int)((size_t)DMODEL * DMODEL / 4);
    dim3 blk(256);
    dim3 grid_proj(DMODEL / 128, M_rows / 128, 1);

    // 1) Projections -> bf16 hi/lo Q/K/V
    split_bf16<<<(nact4 + 255) / 256, blk>>>(q, ahi, alo, nact4);
    split_bf16<<<(nw4 + 255) / 256, blk>>>(w_q, whi, wlo, nw4);
    gemm_nt_tc<1><<<grid_proj, blk, NT_SMEM>>>(ahi, alo, whi, wlo, nullptr, qhi, qlo,
        DMODEL, DMODEL, DMODEL, DMODEL, 0, 0, 0, 0, 0, 0, 1.0f);

    split_bf16<<<(nact4 + 255) / 256, blk>>>(k, ahi, alo, nact4);
    split_bf16<<<(nw4 + 255) / 256, blk>>>(w_k, whi, wlo, nw4);
    gemm_nt_tc<1><<<grid_proj, blk, NT_SMEM>>>(ahi, alo, whi, wlo, nullptr, khi, klo,
        DMODEL, DMODEL, DMODEL, DMODEL, 0, 0, 0, 0, 0, 0, 1.0f);

    split_bf16<<<(nact4 + 255) / 256, blk>>>(v, ahi, alo, nact4);
    split_bf16<<<(nw4 + 255) / 256, blk>>>(w_v, whi, wlo, nw4);
    gemm_nt_tc<1><<<grid_proj, blk, NT_SMEM>>>(ahi, alo, whi, wlo, nullptr, vhi, vlo,
        DMODEL, DMODEL, DMODEL, DMODEL, 0, 0, 0, 0, 0, 0, 1.0f);

    // 2) Logits = Qh @ Kh^T / sqrt(Dk)  (batched over b,h; K=128)
    {
        dim3 grid(S_LEN / 128, S_LEN / 128, NBATCH * NHEADS);
        gemm_nt_tc<0><<<grid, blk, NT_SMEM>>>(qhi, qlo, khi, klo, glog, nullptr, nullptr,
            DK, DMODEL, DMODEL, S_LEN,
            SD, (size_t)DK, SD, (size_t)DK,
            (size_t)NHEADS * SS, SS, inv_sqrt_dk);
    }

    // 3) Softmax -> P hi/lo
    softmax_split<<<NBATCH * NHEADS * S_LEN, blk>>>(glog, phi, plo);

    // 4) Attn = P @ Vh  (batched NN; N=128 per head), head-interleaved hi/lo out
    {
        dim3 grid(1, S_LEN / 128, NBATCH * NHEADS);
        gemm_nn_tc<<<grid, blk, PV_SMEM>>>(phi, plo, vhi, vlo, athi, atlo,
            S_LEN, S_LEN, DMODEL, DMODEL,
            (size_t)NHEADS * SS, SS, SD, (size_t)DK, SD, (size_t)DK);
    }

    // 5) Output projection -> fp32 d_out
    split_bf16<<<(nw4 + 255) / 256, blk>>>(w_o, whi, wlo, nw4);
    gemm_nt_tc<0><<<grid_proj, blk, NT_SMEM>>>(athi, atlo, whi, wlo, out, nullptr, nullptr,
        DMODEL, DMODEL, DMODEL, DMODEL, 0, 0, 0, 0, 0, 0, 1.0f);
}

// round 7
// speedup vs baseline: 3.5756x; 1.1760x over previous
#include <cuda_runtime.h>
#include <cuda_bf16.h>
#include <math.h>
#include <stdint.h>

#define S_LEN   2048
#define DMODEL  2048
#define NHEADS  16
#define DK      128
#define NBATCH  4

// ---------------- static device scratch ------------------------------------
__device__ __nv_bfloat16 g_qhi[(size_t)NBATCH * S_LEN * DMODEL];
__device__ __nv_bfloat16 g_qlo[(size_t)NBATCH * S_LEN * DMODEL];
__device__ __nv_bfloat16 g_khi[(size_t)NBATCH * S_LEN * DMODEL];
__device__ __nv_bfloat16 g_klo[(size_t)NBATCH * S_LEN * DMODEL];
__device__ __nv_bfloat16 g_vhi[(size_t)NBATCH * S_LEN * DMODEL];
__device__ __nv_bfloat16 g_vlo[(size_t)NBATCH * S_LEN * DMODEL];
__device__ __nv_bfloat16 g_athi[(size_t)NBATCH * S_LEN * DMODEL];
__device__ __nv_bfloat16 g_atlo[(size_t)NBATCH * S_LEN * DMODEL];
__device__ __nv_bfloat16 g_act_hi[(size_t)NBATCH * S_LEN * DMODEL];
__device__ __nv_bfloat16 g_act_lo[(size_t)NBATCH * S_LEN * DMODEL];
__device__ __nv_bfloat16 g_w_hi[(size_t)DMODEL * DMODEL];
__device__ __nv_bfloat16 g_w_lo[(size_t)DMODEL * DMODEL];

// ======================= PTX helpers =======================================
__device__ __forceinline__ uint32_t smem_u32(const void* p) {
    uint32_t a;
    asm("{ .reg .u64 t; cvta.to.shared.u64 t, %1; cvt.u32.u64 %0, t; }" : "=r"(a) : "l"(p));
    return a;
}
#define CP_ASYNC16(dst, src) asm volatile("cp.async.cg.shared.global [%0], [%1], 16;" :: "r"(dst), "l"(src))
#define CP_COMMIT()          asm volatile("cp.async.commit_group;" ::: "memory")
#define CP_WAIT0()           asm volatile("cp.async.wait_group 0;" ::: "memory")
#define CP_WAIT1()           asm volatile("cp.async.wait_group 1;" ::: "memory")

#define LDSM_X4(r0, r1, r2, r3, addr) \
    asm volatile("ldmatrix.sync.aligned.m8n8.x4.shared.b16 {%0,%1,%2,%3}, [%4];" \
        : "=r"(r0), "=r"(r1), "=r"(r2), "=r"(r3) : "r"(addr))
#define LDSM_X4_T(r0, r1, r2, r3, addr) \
    asm volatile("ldmatrix.sync.aligned.m8n8.x4.trans.shared.b16 {%0,%1,%2,%3}, [%4];" \
        : "=r"(r0), "=r"(r1), "=r"(r2), "=r"(r3) : "r"(addr))

#define MMA_BF16(c, a, b0, b1) \
    asm volatile("mma.sync.aligned.m16n8k16.row.col.f32.bf16.bf16.f32 " \
        "{%0,%1,%2,%3},{%4,%5,%6,%7},{%8,%9},{%0,%1,%2,%3};" \
        : "+f"((c)[0]), "+f"((c)[1]), "+f"((c)[2]), "+f"((c)[3]) \
        : "r"((a)[0]), "r"((a)[1]), "r"((a)[2]), "r"((a)[3]), "r"(b0), "r"(b1))

__device__ __forceinline__ void split2(float x, __nv_bfloat16& h, __nv_bfloat16& l) {
    h = __float2bfloat16_rn(x);
    l = __float2bfloat16_rn(x - __bfloat162float(h));
}
__device__ __forceinline__ uint32_t packb(__nv_bfloat16 a, __nv_bfloat16 b) {
    __nv_bfloat162 t(a, b);           // a -> low half (even col), b -> high
    return *(uint32_t*)&t;
}

// ===========================================================================
// bf16x3 NT GEMM (projections): C[m,n] = alpha * sum_k A[m,k]*B[n,k]
// ===========================================================================
#define LDSB 80
#define ARR_BYTES (128 * LDSB)
#define STG_BYTES (4 * ARR_BYTES)
#define NT_SMEM (2 * STG_BYTES)

template<int OUTMODE>
__global__ __launch_bounds__(256) void gemm_nt_tc(
    const __nv_bfloat16* __restrict__ Ahi, const __nv_bfloat16* __restrict__ Alo,
    const __nv_bfloat16* __restrict__ Bhi, const __nv_bfloat16* __restrict__ Blo,
    float* __restrict__ Cf, __nv_bfloat16* __restrict__ Chi, __nv_bfloat16* __restrict__ Clo,
    int K, int ldc, float alpha)
{
    extern __shared__ char smem[];
    const uint32_t sb = smem_u32(smem);
    const int tid  = threadIdx.x;
    const int lane = tid & 31, wid = tid >> 5;
    const int wm   = wid & 3, wn = wid >> 2;
    const int row0 = blockIdx.y * 128;
    const int col0 = blockIdx.x * 128;

    const __nv_bfloat16* gsrc[4] = {Ahi, Alo, Bhi, Blo};
    const int nchunk = K >> 5;

    auto issue_stage = [&](int kt, int s) {
        const int k0 = kt << 5;
        const uint32_t sbase = sb + s * STG_BYTES;
#pragma unroll
        for (int a = 0; a < 4; a++) {
            const __nv_bfloat16* g = gsrc[a];
            const int rbase = (a < 2) ? row0 : col0;
#pragma unroll
            for (int i = 0; i < 2; i++) {
                const int c = tid + i * 256;
                const int r = c >> 2, q = c & 3;
                const __nv_bfloat16* src = g + (size_t)(rbase + r) * K + k0 + q * 8;
                const uint32_t dst = sbase + a * ARR_BYTES + r * LDSB + q * 16;
                CP_ASYNC16(dst, src);
            }
        }
        CP_COMMIT();
    };

    float acc[2][8][4];
#pragma unroll
    for (int mt = 0; mt < 2; mt++)
#pragma unroll
        for (int nt = 0; nt < 8; nt++)
#pragma unroll
            for (int r = 0; r < 4; r++) acc[mt][nt][r] = 0.0f;

    const int arow  = wm * 32 + (lane & 15);
    const int acolb = ((lane >> 4) << 3) * 2;
    const int brow  = wn * 64 + (lane & 7) + ((lane >> 4) & 1) * 8;
    const int bcolb = (((lane >> 3) & 1) << 3) * 2;

    auto compute_stage = [&](int s) {
        const uint32_t sbase = sb + s * STG_BYTES;
        const uint32_t sAhi = sbase;
        const uint32_t sAlo = sbase + ARR_BYTES;
        const uint32_t sBhi = sbase + 2 * ARR_BYTES;
        const uint32_t sBlo = sbase + 3 * ARR_BYTES;
#pragma unroll
        for (int h = 0; h < 2; h++) {
            const int kb = h * 32;
            uint32_t ah[2][4], al[2][4];
            {
                uint32_t a0 = sAhi + arow * LDSB + acolb + kb;
                LDSM_X4(ah[0][0], ah[0][1], ah[0][2], ah[0][3], a0);
                LDSM_X4(ah[1][0], ah[1][1], ah[1][2], ah[1][3], a0 + 16 * LDSB);
                uint32_t l0 = sAlo + arow * LDSB + acolb + kb;
                LDSM_X4(al[0][0], al[0][1], al[0][2], al[0][3], l0);
                LDSM_X4(al[1][0], al[1][1], al[1][2], al[1][3], l0 + 16 * LDSB);
            }
#pragma unroll
            for (int np = 0; np < 4; np++) {
                uint32_t bh[4], bl[4];
                const uint32_t bo = (brow + np * 16) * LDSB + bcolb + kb;
                LDSM_X4(bh[0], bh[1], bh[2], bh[3], sBhi + bo);
                LDSM_X4(bl[0], bl[1], bl[2], bl[3], sBlo + bo);
#pragma unroll
                for (int mt = 0; mt < 2; mt++) {
#pragma unroll
                    for (int u = 0; u < 2; u++) {
                        float* c = acc[mt][np * 2 + u];
                        MMA_BF16(c, ah[mt], bh[2 * u], bh[2 * u + 1]);
                        MMA_BF16(c, ah[mt], bl[2 * u], bl[2 * u + 1]);
                        MMA_BF16(c, al[mt], bh[2 * u], bh[2 * u + 1]);
                    }
                }
            }
        }
    };

    issue_stage(0, 0);
    if (nchunk > 1) issue_stage(1, 1);
    for (int t = 0; t < nchunk; t++) {
        if (t + 2 < nchunk) { CP_WAIT1(); } else { CP_WAIT0(); }
        __syncthreads();
        compute_stage(t & 1);
        __syncthreads();
        if (t + 2 < nchunk) issue_stage(t + 2, t & 1);
    }

#pragma unroll
    for (int mt = 0; mt < 2; mt++) {
#pragma unroll
        for (int nt = 0; nt < 8; nt++) {
            const int r  = row0 + wm * 32 + mt * 16 + (lane >> 2);
            const int cc = col0 + wn * 64 + nt * 8 + (lane & 3) * 2;
            if (OUTMODE == 0) {
                float* p = Cf + (size_t)r * ldc + cc;
                *(float2*)p = make_float2(acc[mt][nt][0] * alpha, acc[mt][nt][1] * alpha);
                *(float2*)(p + 8 * ldc) = make_float2(acc[mt][nt][2] * alpha, acc[mt][nt][3] * alpha);
            } else {
                __nv_bfloat16 h0, h1, l0, l1;
                split2(acc[mt][nt][0] * alpha, h0, l0);
                split2(acc[mt][nt][1] * alpha, h1, l1);
                *(__nv_bfloat162*)(Chi + (size_t)r * ldc + cc) = __nv_bfloat162(h0, h1);
                *(__nv_bfloat162*)(Clo + (size_t)r * ldc + cc) = __nv_bfloat162(l0, l1);
                split2(acc[mt][nt][2] * alpha, h0, l0);
                split2(acc[mt][nt][3] * alpha, h1, l1);
                *(__nv_bfloat162*)(Chi + (size_t)(r + 8) * ldc + cc) = __nv_bfloat162(h0, h1);
                *(__nv_bfloat162*)(Clo + (size_t)(r + 8) * ldc + cc) = __nv_bfloat162(l0, l1);
            }
        }
    }
}

// ===========================================================================
// Fused flash attention: per CTA = 128 Q rows x one (b,h).
// Q hi/lo persistent in smem; loop over 32 K/V blocks of 64 s-rows,
// double-buffered cp.async. S = bf16x3 QK^T, online softmax, PV = bf16x3
// with register hi/lo split of P. Output written as bf16 hi/lo attn.
// ===========================================================================
#define FA_LDSB    272
#define FA_QTILE   (128 * FA_LDSB)              // 34816
#define FA_KVTILE  (64 * FA_LDSB)               // 17408
#define FA_STG     (4 * FA_KVTILE)              // 69632
#define FA_SMEM    (2 * FA_QTILE + 2 * FA_STG)  // 208896

__global__ __launch_bounds__(256, 1) void fused_attn(
    const __nv_bfloat16* __restrict__ Qhi, const __nv_bfloat16* __restrict__ Qlo,
    const __nv_bfloat16* __restrict__ Khi, const __nv_bfloat16* __restrict__ Klo,
    const __nv_bfloat16* __restrict__ Vhi, const __nv_bfloat16* __restrict__ Vlo,
    __nv_bfloat16* __restrict__ Ohi, __nv_bfloat16* __restrict__ Olo)
{
    extern __shared__ char smem[];
    const uint32_t sb = smem_u32(smem);
    const int tid  = threadIdx.x;
    const int lane = tid & 31, wid = tid >> 5;       // 8 warps x 16 rows
    const int qrow0 = blockIdx.x * 128;
    const int z  = blockIdx.y;
    const int bb = z >> 4, hh = z & 15;
    const size_t base = (size_t)bb * S_LEN * DMODEL + (size_t)hh * DK;

    const __nv_bfloat16* qsrc[2] = {Qhi + base, Qlo + base};
    const __nv_bfloat16* kvsrc[4] = {Khi + base, Klo + base, Vhi + base, Vlo + base};

    const uint32_t sQ = sb;                          // Qhi, Qlo tiles
    const uint32_t sKV = sb + 2 * FA_QTILE;

    // ---- prologue: Q tiles + stage 0 in group 0, stage 1 in group 1 -------
#pragma unroll
    for (int i = 0; i < 16; i++) {
        const int c = tid + i * 256;                 // 0..4095
        const int t = c >> 11, rem = c & 2047;
        const int r = rem >> 4, q = rem & 15;
        CP_ASYNC16(sQ + t * FA_QTILE + r * FA_LDSB + q * 16,
                   qsrc[t] + (size_t)(qrow0 + r) * DMODEL + q * 8);
    }
    auto issue_stage = [&](int j, int s) {
        const int s0 = j << 6;
        const uint32_t sbase = sKV + s * FA_STG;
#pragma unroll
        for (int i = 0; i < 16; i++) {
            const int c = tid + i * 256;             // 0..4095
            const int t = c >> 10, rem = c & 1023;
            const int r = rem >> 4, q = rem & 15;
            CP_ASYNC16(sbase + t * FA_KVTILE + r * FA_LDSB + q * 16,
                       kvsrc[t] + (size_t)(s0 + r) * DMODEL + q * 8);
        }
        CP_COMMIT();
    };
    issue_stage(0, 0);
    issue_stage(1, 1);

    // ---- per-thread state --------------------------------------------------
    float accO[16][4];
#pragma unroll
    for (int nt = 0; nt < 16; nt++)
#pragma unroll
        for (int r = 0; r < 4; r++) accO[nt][r] = 0.0f;
    float mrow[2] = {-1e30f, -1e30f};
    float lrow[2] = {0.0f, 0.0f};
    const float csc = 0.08838834764831845f;          // 1/sqrt(128)

    // fragment addressing
    const int arow  = wid * 16 + (lane & 15);
    const int acolb = (lane >> 4) * 16;
    const int brow  = (lane & 7) + ((lane >> 4) & 1) * 8;
    const int bcolb = ((lane >> 3) & 1) * 16;
    const int btr   = (lane & 7) + ((lane >> 3) & 1) * 8;
    const int btc   = ((lane >> 4) & 1) * 8;

    const int NITER = S_LEN / 64;                    // 32
    for (int j = 0; j < NITER; j++) {
        if (j + 2 < NITER) { CP_WAIT1(); } else { CP_WAIT0(); }
        __syncthreads();
        const uint32_t st = sKV + (j & 1) * FA_STG;
        const uint32_t sKh = st;
        const uint32_t sKl = st + FA_KVTILE;
        const uint32_t sVh = st + 2 * FA_KVTILE;
        const uint32_t sVl = st + 3 * FA_KVTILE;

        // ---- S = Q K^T (3-pass), 128m x 64n, K=128 -------------------------
        float sacc[8][4];
#pragma unroll
        for (int nt = 0; nt < 8; nt++)
#pragma unroll
            for (int r = 0; r < 4; r++) sacc[nt][r] = 0.0f;

#pragma unroll
        for (int kst = 0; kst < 8; kst++) {
            const int kb = kst * 32;
            uint32_t qh[4], ql[4];
            LDSM_X4(qh[0], qh[1], qh[2], qh[3], sQ + arow * FA_LDSB + acolb + kb);
            LDSM_X4(ql[0], ql[1], ql[2], ql[3], sQ + FA_QTILE + arow * FA_LDSB + acolb + kb);
#pragma unroll
            for (int np = 0; np < 4; np++) {
                const uint32_t bo = (uint32_t)(brow + np * 16) * FA_LDSB + bcolb + kb;
                uint32_t kh[4], kl[4];
                LDSM_X4(kh[0], kh[1], kh[2], kh[3], sKh + bo);
                LDSM_X4(kl[0], kl[1], kl[2], kl[3], sKl + bo);
#pragma unroll
                for (int u = 0; u < 2; u++) {
                    float* c = sacc[np * 2 + u];
                    MMA_BF16(c, qh, kh[2 * u], kh[2 * u + 1]);
                    MMA_BF16(c, qh, kl[2 * u], kl[2 * u + 1]);
                    MMA_BF16(c, ql, kh[2 * u], kh[2 * u + 1]);
                }
            }
        }

        // ---- online softmax ------------------------------------------------
        float mnew[2] = {mrow[0], mrow[1]};
#pragma unroll
        for (int nt = 0; nt < 8; nt++) {
            mnew[0] = fmaxf(mnew[0], fmaxf(sacc[nt][0], sacc[nt][1]));
            mnew[1] = fmaxf(mnew[1], fmaxf(sacc[nt][2], sacc[nt][3]));
        }
#pragma unroll
        for (int o = 1; o <= 2; o <<= 1) {
            mnew[0] = fmaxf(mnew[0], __shfl_xor_sync(0xffffffffu, mnew[0], o));
            mnew[1] = fmaxf(mnew[1], __shfl_xor_sync(0xffffffffu, mnew[1], o));
        }
        const float sc0 = __expf((mrow[0] - mnew[0]) * csc);
        const float sc1 = __expf((mrow[1] - mnew[1]) * csc);
        mrow[0] = mnew[0]; mrow[1] = mnew[1];
        lrow[0] *= sc0; lrow[1] *= sc1;
#pragma unroll
        for (int nt = 0; nt < 16; nt++) {
            accO[nt][0] *= sc0; accO[nt][1] *= sc0;
            accO[nt][2] *= sc1; accO[nt][3] *= sc1;
        }

        // p = exp(csc*(s - m)), split hi/lo, pack to A fragments
        uint32_t ph[4][4], pl[4][4];
        float ls0 = 0.0f, ls1 = 0.0f;
#pragma unroll
        for (int t2 = 0; t2 < 4; t2++) {
#pragma unroll
            for (int half = 0; half < 2; half++) {
                float* s = sacc[2 * t2 + half];
                float p0 = __expf((s[0] - mnew[0]) * csc);
                float p1 = __expf((s[1] - mnew[0]) * csc);
                float p2 = __expf((s[2] - mnew[1]) * csc);
                float p3 = __expf((s[3] - mnew[1]) * csc);
                ls0 += p0 + p1; ls1 += p2 + p3;
                __nv_bfloat16 h0, h1, h2, h3, l0, l1, l2, l3;
                split2(p0, h0, l0); split2(p1, h1, l1);
                split2(p2, h2, l2); split2(p3, h3, l3);
                ph[t2][2 * half + 0] = packb(h0, h1);   // wrong index? see below
                ph[t2][2 * half + 1] = packb(h2, h3);
                pl[t2][2 * half + 0] = packb(l0, l1);
                pl[t2][2 * half + 1] = packb(l2, l3);
            }
        }
        // A-frag ordering fix: a0=(rows r, k 0-7)=tile even c0c1; a1=(rows r+8, k0-7)=tile even c2c3;
        // a2=(rows r, k8-15)=tile odd c0c1; a3=(rows r+8, k8-15)=tile odd c2c3.
        // The packing above already places: half=0(even tile): ph[0]=c0c1, ph[1]=c2c3;
        // half=1(odd tile): ph[2]=c0c1, ph[3]=c2c3.  => matches (a0,a1,a2,a3). OK.
        lrow[0] += ls0; lrow[1] += ls1;

        // ---- O += P V (3-pass), k = 64 s-cols ------------------------------
#pragma unroll
        for (int t2 = 0; t2 < 4; t2++) {
#pragma unroll
            for (int np = 0; np < 8; np++) {
                const uint32_t bo = (uint32_t)(t2 * 16 + btr) * FA_LDSB + (np * 16 + btc) * 2;
                uint32_t vh[4], vl[4];
                LDSM_X4_T(vh[0], vh[1], vh[2], vh[3], sVh + bo);
                LDSM_X4_T(vl[0], vl[1], vl[2], vl[3], sVl + bo);
#pragma unroll
                for (int u = 0; u < 2; u++) {
                    float* c = accO[np * 2 + u];
                    MMA_BF16(c, ph[t2], vh[2 * u], vh[2 * u + 1]);
                    MMA_BF16(c, ph[t2], vl[2 * u], vl[2 * u + 1]);
                    MMA_BF16(c, pl[t2], vh[2 * u], vh[2 * u + 1]);
                }
            }
        }

        __syncthreads();
        if (j + 2 < NITER) issue_stage(j + 2, j & 1);
    }

    // ---- epilogue ----------------------------------------------------------
#pragma unroll
    for (int o = 1; o <= 2; o <<= 1) {
        lrow[0] += __shfl_xor_sync(0xffffffffu, lrow[0], o);
        lrow[1] += __shfl_xor_sync(0xffffffffu, lrow[1], o);
    }
    const float inv0 = 1.0f / lrow[0];
    const float inv1 = 1.0f / lrow[1];
    const int r0 = qrow0 + wid * 16 + (lane >> 2);
#pragma unroll
    for (int nt = 0; nt < 16; nt++) {
        const int cc = nt * 8 + (lane & 3) * 2;
        __nv_bfloat16 h0, h1, l0, l1;
        split2(accO[nt][0] * inv0, h0, l0);
        split2(accO[nt][1] * inv0, h1, l1);
        *(__nv_bfloat162*)(Ohi + base + (size_t)r0 * DMODEL + cc) = __nv_bfloat162(h0, h1);
        *(__nv_bfloat162*)(Olo + base + (size_t)r0 * DMODEL + cc) = __nv_bfloat162(l0, l1);
        split2(accO[nt][2] * inv1, h0, l0);
        split2(accO[nt][3] * inv1, h1, l1);
        *(__nv_bfloat162*)(Ohi + base + (size_t)(r0 + 8) * DMODEL + cc) = __nv_bfloat162(h0, h1);
        *(__nv_bfloat162*)(Olo + base + (size_t)(r0 + 8) * DMODEL + cc) = __nv_bfloat162(l0, l1);
    }
}

// ===========================================================================
// fp32 -> bf16 hi/lo split
// ===========================================================================
__global__ __launch_bounds__(256) void split_bf16(
    const float* __restrict__ x, __nv_bfloat16* __restrict__ hi,
    __nv_bfloat16* __restrict__ lo, int n4)
{
    int i = blockIdx.x * 256 + threadIdx.x;
    if (i >= n4) return;
    float4 v = ((const float4*)x)[i];
    __nv_bfloat16 h0, h1, h2, h3, l0, l1, l2, l3;
    split2(v.x, h0, l0); split2(v.y, h1, l1);
    split2(v.z, h2, l2); split2(v.w, h3, l3);
    ((__nv_bfloat162*)hi)[2 * i + 0] = __nv_bfloat162(h0, h1);
    ((__nv_bfloat162*)hi)[2 * i + 1] = __nv_bfloat162(h2, h3);
    ((__nv_bfloat162*)lo)[2 * i + 0] = __nv_bfloat162(l0, l1);
    ((__nv_bfloat162*)lo)[2 * i + 1] = __nv_bfloat162(l2, l3);
}

// ---------------------------------------------------------------------------
extern "C" void kernel_launch(void* const* d_in, const int* in_sizes, int n_in,
                              void* d_out, int out_size)
{
    const float* q   = (const float*)d_in[0];
    const float* k   = (const float*)d_in[1];
    const float* v   = (const float*)d_in[2];
    const float* w_q = (const float*)d_in[3];
    const float* w_k = (const float*)d_in[4];
    const float* w_v = (const float*)d_in[5];
    const float* w_o = (const float*)d_in[6];
    float* out = (float*)d_out;

    __nv_bfloat16 *qhi, *qlo, *khi, *klo, *vhi, *vlo, *athi, *atlo;
    __nv_bfloat16 *ahi, *alo, *whi, *wlo;
    cudaGetSymbolAddress((void**)&qhi, g_qhi);  cudaGetSymbolAddress((void**)&qlo, g_qlo);
    cudaGetSymbolAddress((void**)&khi, g_khi);  cudaGetSymbolAddress((void**)&klo, g_klo);
    cudaGetSymbolAddress((void**)&vhi, g_vhi);  cudaGetSymbolAddress((void**)&vlo, g_vlo);
    cudaGetSymbolAddress((void**)&athi, g_athi); cudaGetSymbolAddress((void**)&atlo, g_atlo);
    cudaGetSymbolAddress((void**)&ahi, g_act_hi); cudaGetSymbolAddress((void**)&alo, g_act_lo);
    cudaGetSymbolAddress((void**)&whi, g_w_hi);  cudaGetSymbolAddress((void**)&wlo, g_w_lo);

    cudaFuncSetAttribute(gemm_nt_tc<0>, cudaFuncAttributeMaxDynamicSharedMemorySize, NT_SMEM);
    cudaFuncSetAttribute(gemm_nt_tc<1>, cudaFuncAttributeMaxDynamicSharedMemorySize, NT_SMEM);
    cudaFuncSetAttribute(fused_attn, cudaFuncAttributeMaxDynamicSharedMemorySize, FA_SMEM);

    const int M_rows = NBATCH * S_LEN;
    const int nact4 = (int)((size_t)M_rows * DMODEL / 4);
    const int nw4   = (int)((size_t)DMODEL * DMODEL / 4);
    dim3 blk(256);
    dim3 grid_proj(DMODEL / 128, M_rows / 128);

    // 1) Projections -> bf16 hi/lo Q/K/V
    split_bf16<<<(nact4 + 255) / 256, blk>>>(q, ahi, alo, nact4);
    split_bf16<<<(nw4 + 255) / 256, blk>>>(w_q, whi, wlo, nw4);
    gemm_nt_tc<1><<<grid_proj, blk, NT_SMEM>>>(ahi, alo, whi, wlo, nullptr, qhi, qlo,
                                               DMODEL, DMODEL, 1.0f);

    split_bf16<<<(nact4 + 255) / 256, blk>>>(k, ahi, alo, nact4);
    split_bf16<<<(nw4 + 255) / 256, blk>>>(w_k, whi, wlo, nw4);
    gemm_nt_tc<1><<<grid_proj, blk, NT_SMEM>>>(ahi, alo, whi, wlo, nullptr, khi, klo,
                                               DMODEL, DMODEL, 1.0f);

    split_bf16<<<(nact4 + 255) / 256, blk>>>(v, ahi, alo, nact4);
    split_bf16<<<(nw4 + 255) / 256, blk>>>(w_v, whi, wlo, nw4);
    gemm_nt_tc<1><<<grid_proj, blk, NT_SMEM>>>(ahi, alo, whi, wlo, nullptr, vhi, vlo,
                                               DMODEL, DMODEL, 1.0f);

    // 2-4) Fused attention (QK^T -> online softmax -> PV), attn as hi/lo
    {
        dim3 grid(S_LEN / 128, NBATCH * NHEADS);
        fused_attn<<<grid, blk, FA_SMEM>>>(qhi, qlo, khi, klo, vhi, vlo, athi, atlo);
    }

    // 5) Output projection -> fp32 d_out
    split_bf16<<<(nw4 + 255) / 256, blk>>>(w_o, whi, wlo, nw4);
    gemm_nt_tc<0><<<grid_proj, blk, NT_SMEM>>>(athi, atlo, whi, wlo, out, nullptr, nullptr,
                                               DMODEL, DMODEL, 1.0f);
}